// round 1
// baseline (speedup 1.0000x reference)
#include <cuda_runtime.h>
#include <math.h>
#include <stdint.h>

// Problem constants
#define BB     2
#define TT     2048
#define CC     2048
#define NHH    16
#define HDD    128
#define NQKV   6144          // 3*C
#define MROWS  4096          // B*T

// Scratch (device globals; no allocation allowed)
__device__ float g_qkv[(size_t)MROWS * NQKV];   // 96 MB
__device__ float g_y[(size_t)MROWS * CC];       // 32 MB

#define NEG_INF (__int_as_float(0xff800000))

// ---------------------------------------------------------------------------
// SGEMM: out[m,n] = sum_k A[m,k] * W[n,k] + bias[n]
// A: [M,K] row-major, W: [N,K] row-major (i.e. computes A @ W^T + b)
// Tile 128x128, BK=8, 256 threads, 8x8 per-thread microtile.
// M, N multiples of 128; K multiple of 8.
// ---------------------------------------------------------------------------
__global__ void __launch_bounds__(256) sgemm_bias_kernel(
    const float* __restrict__ A, const float* __restrict__ W,
    const float* __restrict__ bias, float* __restrict__ out,
    int M, int N, int K)
{
    __shared__ float As[8][128];
    __shared__ float Bs[8][128];

    const int t  = threadIdx.x;
    const int tx = t & 15;        // 0..15 -> 8 output cols each
    const int ty = t >> 4;        // 0..15 -> 8 output rows each

    const int lrow = t >> 1;          // 0..127
    const int lk   = (t & 1) << 2;    // 0 or 4

    const float* Ap = A + (size_t)(blockIdx.y * 128 + lrow) * K + lk;
    const float* Wp = W + (size_t)(blockIdx.x * 128 + lrow) * K + lk;

    float acc[8][8];
#pragma unroll
    for (int i = 0; i < 8; i++)
#pragma unroll
        for (int j = 0; j < 8; j++) acc[i][j] = 0.f;

    for (int k0 = 0; k0 < K; k0 += 8) {
        float4 a4 = *(const float4*)(Ap + k0);
        float4 w4 = *(const float4*)(Wp + k0);
        __syncthreads();
        As[lk + 0][lrow] = a4.x; As[lk + 1][lrow] = a4.y;
        As[lk + 2][lrow] = a4.z; As[lk + 3][lrow] = a4.w;
        Bs[lk + 0][lrow] = w4.x; Bs[lk + 1][lrow] = w4.y;
        Bs[lk + 2][lrow] = w4.z; Bs[lk + 3][lrow] = w4.w;
        __syncthreads();
#pragma unroll
        for (int kk = 0; kk < 8; kk++) {
            float4 a0 = *(const float4*)&As[kk][ty * 8];
            float4 a1 = *(const float4*)&As[kk][ty * 8 + 4];
            float4 b0 = *(const float4*)&Bs[kk][tx * 8];
            float4 b1 = *(const float4*)&Bs[kk][tx * 8 + 4];
            float ar[8] = {a0.x, a0.y, a0.z, a0.w, a1.x, a1.y, a1.z, a1.w};
            float br[8] = {b0.x, b0.y, b0.z, b0.w, b1.x, b1.y, b1.z, b1.w};
#pragma unroll
            for (int i = 0; i < 8; i++)
#pragma unroll
                for (int j = 0; j < 8; j++)
                    acc[i][j] += ar[i] * br[j];
        }
    }

    const int m0 = blockIdx.y * 128 + ty * 8;
    const int n0 = blockIdx.x * 128 + tx * 8;
    float bv[8];
#pragma unroll
    for (int j = 0; j < 8; j++) bv[j] = bias[n0 + j];
#pragma unroll
    for (int i = 0; i < 8; i++) {
        float* orow = out + (size_t)(m0 + i) * N + n0;
#pragma unroll
        for (int j = 0; j < 8; j++) orow[j] = acc[i][j] + bv[j];
    }
}

// ---------------------------------------------------------------------------
// RoPE applied in-place to the q and k sections of qkv [MROWS, 6144].
// Interleaved pairs (even, odd) within each head's 128 dims.
// Matches reference fp32 math: theta = 1/powf(10000, i/64); ang = t*theta.
// ---------------------------------------------------------------------------
__global__ void rope_kernel(float* __restrict__ qkv)
{
    int idx = blockIdx.x * blockDim.x + threadIdx.x;   // one pair per thread
    if (idx >= MROWS * 2048) return;                   // 2048 pairs/row (q+k)
    int row = idx >> 11;
    int p   = idx & 2047;
    int tpos = row & (TT - 1);                         // row % T

    int col = (p < 1024) ? (2 * p) : (2048 + 2 * (p - 1024));
    int d   = col & (HDD - 1);                         // dim within head (even)
    int i   = d >> 1;                                  // pair index 0..63

    float theta = 1.0f / powf(10000.0f, (float)i / 64.0f);
    float ang   = (float)tpos * theta;
    float c = cosf(ang);
    float s = sinf(ang);

    float2* ptr = (float2*)(qkv + (size_t)row * NQKV + col);
    float2 v = *ptr;
    float2 o;
    o.x = v.x * c - v.y * s;
    o.y = v.x * s + v.y * c;
    *ptr = o;
}

// ---------------------------------------------------------------------------
// Flash attention (fp32, causal). One block per (b,h,qtile of 64).
// Reads q/k/v directly from qkv scratch ([row, section + h*128 + d]).
// Writes y in [B,T,C] layout.
// ---------------------------------------------------------------------------
#define QP 129   // pitch for Qs/Ks (conflict-free column reads)
#define SP 65    // pitch for score tile
#define FLASH_SMEM_FLOATS (64 * QP + 64 * QP + 64 * 128 + 64 * SP + 3 * 64)
#define FLASH_SMEM_BYTES  (FLASH_SMEM_FLOATS * 4)

__global__ void __launch_bounds__(256) flash_kernel(
    const float* __restrict__ qkv, float* __restrict__ y)
{
    extern __shared__ float sm[];
    float* Qs   = sm;                 // [64][QP]
    float* Ks   = Qs + 64 * QP;       // [64][QP]
    float* Vs   = Ks + 64 * QP;       // [64][128]
    float* Ss   = Vs + 64 * 128;      // [64][SP]
    float* mrow = Ss + 64 * SP;       // [64]
    float* lrow = mrow + 64;          // [64]
    float* frow = lrow + 64;          // [64]

    const int bh = blockIdx.y;            // 0..31
    const int b  = bh >> 4;
    const int h  = bh & 15;
    const int qt = blockIdx.x;            // 0..31
    const int q0 = qt * 64;

    const int t  = threadIdx.x;
    const int tx = t & 15;
    const int ty = t >> 4;

    const float scale = 0.08838834764831845f;  // 1/sqrt(128)

    // Load Q tile [64][128]
    const float* Qg = qkv + ((size_t)(b * TT + q0)) * NQKV + h * HDD;
    for (int idx = t; idx < 64 * 32; idx += 256) {
        int r  = idx >> 5;
        int c4 = (idx & 31) * 4;
        float4 v = *(const float4*)(Qg + (size_t)r * NQKV + c4);
        Qs[r * QP + c4 + 0] = v.x; Qs[r * QP + c4 + 1] = v.y;
        Qs[r * QP + c4 + 2] = v.z; Qs[r * QP + c4 + 3] = v.w;
    }
    if (t < 64) { mrow[t] = NEG_INF; lrow[t] = 0.f; }

    float o[4][8];
#pragma unroll
    for (int i = 0; i < 4; i++)
#pragma unroll
        for (int j = 0; j < 8; j++) o[i][j] = 0.f;

    for (int kt = 0; kt <= qt; kt++) {
        const int k0 = kt * 64;
        const float* Kg = qkv + ((size_t)(b * TT + k0)) * NQKV + CC + h * HDD;
        const float* Vg = Kg + CC;   // v section is +2C from k section

        __syncthreads();   // previous iteration done with Ks/Vs/Ss
        for (int idx = t; idx < 64 * 32; idx += 256) {
            int r  = idx >> 5;
            int c4 = (idx & 31) * 4;
            float4 kv = *(const float4*)(Kg + (size_t)r * NQKV + c4);
            Ks[r * QP + c4 + 0] = kv.x; Ks[r * QP + c4 + 1] = kv.y;
            Ks[r * QP + c4 + 2] = kv.z; Ks[r * QP + c4 + 3] = kv.w;
            float4 vv = *(const float4*)(Vg + (size_t)r * NQKV + c4);
            *(float4*)(Vs + r * 128 + c4) = vv;
        }
        __syncthreads();

        // S = Q K^T  (64x64 over D=128); each thread computes 4x4
        float sacc[4][4];
#pragma unroll
        for (int i = 0; i < 4; i++)
#pragma unroll
            for (int j = 0; j < 4; j++) sacc[i][j] = 0.f;

#pragma unroll 8
        for (int d = 0; d < 128; d++) {
            float qr[4], kc[4];
#pragma unroll
            for (int i = 0; i < 4; i++) qr[i] = Qs[(ty * 4 + i) * QP + d];
#pragma unroll
            for (int j = 0; j < 4; j++) kc[j] = Ks[(tx * 4 + j) * QP + d];
#pragma unroll
            for (int i = 0; i < 4; i++)
#pragma unroll
                for (int j = 0; j < 4; j++)
                    sacc[i][j] += qr[i] * kc[j];
        }

        // scale + causal mask + store to Ss
#pragma unroll
        for (int i = 0; i < 4; i++) {
            int qq = q0 + ty * 4 + i;
#pragma unroll
            for (int j = 0; j < 4; j++) {
                int kk = k0 + tx * 4 + j;
                float sv = (kk <= qq) ? sacc[i][j] * scale : NEG_INF;
                Ss[(ty * 4 + i) * SP + tx * 4 + j] = sv;
            }
        }
        __syncthreads();

        // Online softmax: 4 threads per row (16 cols each)
        {
            int r = t >> 2, seg = t & 3;
            float* srow = Ss + r * SP + seg * 16;
            float mx = NEG_INF;
#pragma unroll
            for (int j = 0; j < 16; j++) mx = fmaxf(mx, srow[j]);
            mx = fmaxf(mx, __shfl_xor_sync(0xffffffffu, mx, 1));
            mx = fmaxf(mx, __shfl_xor_sync(0xffffffffu, mx, 2));
            float mo = mrow[r];
            float mnew = fmaxf(mo, mx);
            float sum = 0.f;
#pragma unroll
            for (int j = 0; j < 16; j++) {
                float p = __expf(srow[j] - mnew);
                srow[j] = p;
                sum += p;
            }
            sum += __shfl_xor_sync(0xffffffffu, sum, 1);
            sum += __shfl_xor_sync(0xffffffffu, sum, 2);
            if (seg == 0) {
                float f = __expf(mo - mnew);   // 0 on first tile (mo=-inf)
                lrow[r] = lrow[r] * f + sum;
                mrow[r] = mnew;
                frow[r] = f;
            }
        }
        __syncthreads();

        // O = O*f + P V ; each thread: rows ty*4.., cols tx*8..
        float fr[4];
#pragma unroll
        for (int i = 0; i < 4; i++) fr[i] = frow[ty * 4 + i];
#pragma unroll
        for (int i = 0; i < 4; i++)
#pragma unroll
            for (int j = 0; j < 8; j++) o[i][j] *= fr[i];

#pragma unroll 8
        for (int k = 0; k < 64; k++) {
            float p[4], vv[8];
#pragma unroll
            for (int i = 0; i < 4; i++) p[i] = Ss[(ty * 4 + i) * SP + k];
#pragma unroll
            for (int j = 0; j < 8; j++) vv[j] = Vs[k * 128 + tx * 8 + j];
#pragma unroll
            for (int i = 0; i < 4; i++)
#pragma unroll
                for (int j = 0; j < 8; j++)
                    o[i][j] += p[i] * vv[j];
        }
    }

    // Epilogue: divide by l, write y[b, q0+row, h*128 + col]
    float linv[4];
#pragma unroll
    for (int i = 0; i < 4; i++) linv[i] = 1.0f / lrow[ty * 4 + i];
#pragma unroll
    for (int i = 0; i < 4; i++) {
        int r = q0 + ty * 4 + i;
        float* yrow = y + ((size_t)(b * TT + r)) * CC + h * HDD + tx * 8;
#pragma unroll
        for (int j = 0; j < 8; j++) yrow[j] = o[i][j] * linv[i];
    }
}

// ---------------------------------------------------------------------------
// Launch
// ---------------------------------------------------------------------------
extern "C" void kernel_launch(void* const* d_in, const int* in_sizes, int n_in,
                              void* d_out, int out_size)
{
    const float* x      = (const float*)d_in[0];   // [2,2048,2048]
    const float* w_att  = (const float*)d_in[1];   // [6144,2048]
    const float* b_att  = (const float*)d_in[2];   // [6144]
    const float* w_proj = (const float*)d_in[3];   // [2048,2048]
    const float* b_proj = (const float*)d_in[4];   // [2048]
    float* out = (float*)d_out;                    // [2,2048,2048]

    float* qkv = nullptr;
    float* y   = nullptr;
    cudaGetSymbolAddress((void**)&qkv, g_qkv);
    cudaGetSymbolAddress((void**)&y,   g_y);

    // 1) QKV projection: [4096,6144] = x @ w_att^T + b_att
    sgemm_bias_kernel<<<dim3(NQKV / 128, MROWS / 128), 256>>>(
        x, w_att, b_att, qkv, MROWS, NQKV, CC);

    // 2) RoPE on q and k sections (in place)
    {
        int total = MROWS * 2048;
        rope_kernel<<<(total + 255) / 256, 256>>>(qkv);
    }

    // 3) Causal flash attention -> y [B,T,C]
    cudaFuncSetAttribute(flash_kernel,
                         cudaFuncAttributeMaxDynamicSharedMemorySize,
                         FLASH_SMEM_BYTES);
    flash_kernel<<<dim3(TT / 64, BB * NHH), 256, FLASH_SMEM_BYTES>>>(qkv, y);

    // 4) Output projection: out = y @ w_proj^T + b_proj
    sgemm_bias_kernel<<<dim3(CC / 128, MROWS / 128), 256>>>(
        y, w_proj, b_proj, out, MROWS, CC, CC);
}

// round 3
// speedup vs baseline: 1.8400x; 1.8400x over previous
#include <cuda_runtime.h>
#include <math.h>
#include <stdint.h>

// Problem constants
#define BB     2
#define TT     2048
#define CC     2048
#define NHH    16
#define HDD    128
#define NQKV   6144          // 3*C
#define MROWS  4096          // B*T

// Scratch (device globals; no allocation allowed)
__device__ float g_qkv[(size_t)MROWS * NQKV];   // 96 MB
__device__ float g_y[(size_t)MROWS * CC];       // 32 MB

#define NEG_INF (__int_as_float(0xff800000))

__device__ __forceinline__ uint32_t f2tf32(float x) {
    uint32_t r;
    asm("cvt.rna.tf32.f32 %0, %1;" : "=r"(r) : "f"(x));
    return r;
}

// mma.sync m16n8k8 tf32: D += A*B  (acc in-place)
#define MMA_TF32(d, a, b) \
    asm volatile("mma.sync.aligned.m16n8k8.row.col.f32.tf32.tf32.f32 " \
        "{%0,%1,%2,%3}, {%4,%5,%6,%7}, {%8,%9}, {%0,%1,%2,%3};" \
        : "+f"((d)[0]), "+f"((d)[1]), "+f"((d)[2]), "+f"((d)[3]) \
        : "r"((a)[0]), "r"((a)[1]), "r"((a)[2]), "r"((a)[3]), \
          "r"((b)[0]), "r"((b)[1]))

// ---------------------------------------------------------------------------
// TF32 tensor-core GEMM: out[m,n] = sum_k A[m,k]*W[n,k] + bias[n]
// CTA tile 128x128, BK=16, double-buffered smem, 8 warps (4x2), warp 32x64.
// ---------------------------------------------------------------------------
#define GPITCH 20   // 16 + 4 pad (u32), conflict-free fragment loads

__global__ void __launch_bounds__(256) gemm_mma_kernel(
    const float* __restrict__ A, const float* __restrict__ W,
    const float* __restrict__ bias, float* __restrict__ out,
    int M, int N, int K)
{
    __shared__ uint32_t As[2][128][GPITCH];
    __shared__ uint32_t Bs[2][128][GPITCH];

    const int t = threadIdx.x, lane = t & 31, wid = t >> 5;
    const int wm = wid & 3, wn = wid >> 2;
    const int g = lane >> 2, c = lane & 3;
    const int m0 = blockIdx.y * 128, n0 = blockIdx.x * 128;

    // loader mapping: f = t + i*256 -> r = f>>2 (0..127), c4 = (f&3)*4
    const int lr0 = t >> 2;            // i=0 row (0..63)
    const int lc4 = (t & 3) * 4;       // col start 0/4/8/12

    const float* Ag0 = A + (size_t)(m0 + lr0) * K + lc4;
    const float* Ag1 = A + (size_t)(m0 + lr0 + 64) * K + lc4;
    const float* Wg0 = W + (size_t)(n0 + lr0) * K + lc4;
    const float* Wg1 = W + (size_t)(n0 + lr0 + 64) * K + lc4;

    float acc[2][8][4];
#pragma unroll
    for (int i = 0; i < 2; i++)
#pragma unroll
        for (int j = 0; j < 8; j++)
#pragma unroll
            for (int r = 0; r < 4; r++) acc[i][j][r] = 0.f;

    // stage 0 load
    {
        float4 a0 = *(const float4*)(Ag0);
        float4 a1 = *(const float4*)(Ag1);
        float4 b0 = *(const float4*)(Wg0);
        float4 b1 = *(const float4*)(Wg1);
        uint4 u;
        u.x = f2tf32(a0.x); u.y = f2tf32(a0.y); u.z = f2tf32(a0.z); u.w = f2tf32(a0.w);
        *(uint4*)&As[0][lr0][lc4] = u;
        u.x = f2tf32(a1.x); u.y = f2tf32(a1.y); u.z = f2tf32(a1.z); u.w = f2tf32(a1.w);
        *(uint4*)&As[0][lr0 + 64][lc4] = u;
        u.x = f2tf32(b0.x); u.y = f2tf32(b0.y); u.z = f2tf32(b0.z); u.w = f2tf32(b0.w);
        *(uint4*)&Bs[0][lr0][lc4] = u;
        u.x = f2tf32(b1.x); u.y = f2tf32(b1.y); u.z = f2tf32(b1.z); u.w = f2tf32(b1.w);
        *(uint4*)&Bs[0][lr0 + 64][lc4] = u;
    }
    __syncthreads();

    const int nsteps = K >> 4;
    for (int s = 0; s < nsteps; s++) {
        const int cur = s & 1;
        const bool more = (s + 1) < nsteps;
        float4 pa0, pa1, pb0, pb1;
        if (more) {
            const int ko = (s + 1) << 4;
            pa0 = *(const float4*)(Ag0 + ko);
            pa1 = *(const float4*)(Ag1 + ko);
            pb0 = *(const float4*)(Wg0 + ko);
            pb1 = *(const float4*)(Wg1 + ko);
        }
        // compute on smem[cur]
#pragma unroll
        for (int ks = 0; ks < 2; ks++) {
            const int kc = ks * 8;
            uint32_t a[2][4];
#pragma unroll
            for (int mt = 0; mt < 2; mt++) {
                const int row = wm * 32 + mt * 16 + g;
                a[mt][0] = As[cur][row][kc + c];
                a[mt][1] = As[cur][row + 8][kc + c];
                a[mt][2] = As[cur][row][kc + c + 4];
                a[mt][3] = As[cur][row + 8][kc + c + 4];
            }
            uint32_t bfr[8][2];
#pragma unroll
            for (int nf = 0; nf < 8; nf++) {
                const int col = wn * 64 + nf * 8 + g;
                bfr[nf][0] = Bs[cur][col][kc + c];
                bfr[nf][1] = Bs[cur][col][kc + c + 4];
            }
#pragma unroll
            for (int mt = 0; mt < 2; mt++)
#pragma unroll
                for (int nf = 0; nf < 8; nf++)
                    MMA_TF32(acc[mt][nf], a[mt], bfr[nf]);
        }
        if (more) {
            const int nxt = cur ^ 1;
            uint4 u;
            u.x = f2tf32(pa0.x); u.y = f2tf32(pa0.y); u.z = f2tf32(pa0.z); u.w = f2tf32(pa0.w);
            *(uint4*)&As[nxt][lr0][lc4] = u;
            u.x = f2tf32(pa1.x); u.y = f2tf32(pa1.y); u.z = f2tf32(pa1.z); u.w = f2tf32(pa1.w);
            *(uint4*)&As[nxt][lr0 + 64][lc4] = u;
            u.x = f2tf32(pb0.x); u.y = f2tf32(pb0.y); u.z = f2tf32(pb0.z); u.w = f2tf32(pb0.w);
            *(uint4*)&Bs[nxt][lr0][lc4] = u;
            u.x = f2tf32(pb1.x); u.y = f2tf32(pb1.y); u.z = f2tf32(pb1.z); u.w = f2tf32(pb1.w);
            *(uint4*)&Bs[nxt][lr0 + 64][lc4] = u;
        }
        __syncthreads();
    }

    // epilogue: acc (mt rows wm*32+mt*16+g/+8, cols wn*64+nf*8+c*2,+1)
#pragma unroll
    for (int mt = 0; mt < 2; mt++) {
        const int r0 = m0 + wm * 32 + mt * 16 + g;
#pragma unroll
        for (int nf = 0; nf < 8; nf++) {
            const int col = n0 + wn * 64 + nf * 8 + c * 2;
            const float b0v = bias[col], b1v = bias[col + 1];
            float* o0 = out + (size_t)r0 * N + col;
            float* o1 = out + (size_t)(r0 + 8) * N + col;
            o0[0] = acc[mt][nf][0] + b0v;
            o0[1] = acc[mt][nf][1] + b1v;
            o1[0] = acc[mt][nf][2] + b0v;
            o1[1] = acc[mt][nf][3] + b1v;
        }
    }
}

// ---------------------------------------------------------------------------
// RoPE applied in-place to the q and k sections of qkv [MROWS, 6144].
// ---------------------------------------------------------------------------
__global__ void rope_kernel(float* __restrict__ qkv)
{
    int idx = blockIdx.x * blockDim.x + threadIdx.x;   // one pair per thread
    if (idx >= MROWS * 2048) return;
    int row = idx >> 11;
    int p   = idx & 2047;
    int tpos = row & (TT - 1);

    int col = (p < 1024) ? (2 * p) : (2048 + 2 * (p - 1024));
    int d   = col & (HDD - 1);
    int i   = d >> 1;

    float theta = 1.0f / powf(10000.0f, (float)i / 64.0f);
    float ang   = (float)tpos * theta;
    float cs = cosf(ang);
    float sn = sinf(ang);

    float2* ptr = (float2*)(qkv + (size_t)row * NQKV + col);
    float2 v = *ptr;
    float2 o;
    o.x = v.x * cs - v.y * sn;
    o.y = v.x * sn + v.y * cs;
    *ptr = o;
}

// ---------------------------------------------------------------------------
// Flash attention with tf32 mma.sync. One block per (b,h,qtile of 64).
// 8 warps: wm = wid&3 (16-row group), wn = wid>>2 (key/dcol half).
// ---------------------------------------------------------------------------
#define FQP 132   // u32 pitch for Qs/Ks/Vs rows (128 + 4)
#define FSP 68    // float pitch for score tile
#define FLASH_SMEM_U32 (3 * 64 * FQP + 64 * FSP + 3 * 64)
#define FLASH_SMEM_BYTES (FLASH_SMEM_U32 * 4)

__global__ void __launch_bounds__(256) flash_mma_kernel(
    const float* __restrict__ qkv, float* __restrict__ y)
{
    extern __shared__ uint32_t fsm[];
    uint32_t* Qs = fsm;                    // [64][FQP] tf32
    uint32_t* Ks = Qs + 64 * FQP;          // [64][FQP] tf32
    uint32_t* Vs = Ks + 64 * FQP;          // [64][FQP] tf32
    float*    Ss = (float*)(Vs + 64 * FQP);// [64][FSP]
    float* mrow = Ss + 64 * FSP;
    float* lrow = mrow + 64;
    float* frow = lrow + 64;

    const int bh = blockIdx.y, b = bh >> 4, h = bh & 15;
    const int qt = blockIdx.x, q0 = qt * 64;
    const int t = threadIdx.x, lane = t & 31, wid = t >> 5;
    const int wm = wid & 3, wn = wid >> 2;
    const int g = lane >> 2, c = lane & 3;
    const float scale = 0.08838834764831845f;   // 1/sqrt(128)

    // load Q tile [64][128] -> tf32 smem
    const float* Qg = qkv + ((size_t)(b * TT + q0)) * NQKV + h * HDD;
    {
        const int r = wid * 8;   // rows r..r+7 handled by this warp (8 iters)
#pragma unroll
        for (int i = 0; i < 8; i++) {
            float4 v = *(const float4*)(Qg + (size_t)(r + i) * NQKV + lane * 4);
            uint4 u;
            u.x = f2tf32(v.x); u.y = f2tf32(v.y); u.z = f2tf32(v.z); u.w = f2tf32(v.w);
            *(uint4*)(Qs + (r + i) * FQP + lane * 4) = u;
        }
    }
    if (t < 64) { mrow[t] = NEG_INF; lrow[t] = 0.f; }

    const int r0 = wm * 16 + g;   // this thread's primary S/O row (also r0+8)

    float acc_o[8][4];
#pragma unroll
    for (int j = 0; j < 8; j++)
#pragma unroll
        for (int r = 0; r < 4; r++) acc_o[j][r] = 0.f;

    for (int kt = 0; kt <= qt; kt++) {
        const int k0 = kt * 64;
        const float* Kg = qkv + ((size_t)(b * TT + k0)) * NQKV + CC + h * HDD;
        const float* Vg = Kg + CC;

        __syncthreads();  // prior iter done with Ks/Vs/Ss
        {
            const int r = wid * 8;
#pragma unroll
            for (int i = 0; i < 8; i++) {
                float4 kv = *(const float4*)(Kg + (size_t)(r + i) * NQKV + lane * 4);
                uint4 u;
                u.x = f2tf32(kv.x); u.y = f2tf32(kv.y); u.z = f2tf32(kv.z); u.w = f2tf32(kv.w);
                *(uint4*)(Ks + (r + i) * FQP + lane * 4) = u;
                float4 vv = *(const float4*)(Vg + (size_t)(r + i) * NQKV + lane * 4);
                u.x = f2tf32(vv.x); u.y = f2tf32(vv.y); u.z = f2tf32(vv.z); u.w = f2tf32(vv.w);
                *(uint4*)(Vs + (r + i) * FQP + lane * 4) = u;
            }
        }
        __syncthreads();

        // S = Q K^T : warp computes rows [wm*16,+16) x keys [wn*32,+32)
        float acc_s[4][4];
#pragma unroll
        for (int j = 0; j < 4; j++)
#pragma unroll
            for (int r = 0; r < 4; r++) acc_s[j][r] = 0.f;

#pragma unroll
        for (int ks = 0; ks < 16; ks++) {
            const int kc = ks * 8;
            uint32_t a[4];
            a[0] = Qs[r0 * FQP + kc + c];
            a[1] = Qs[(r0 + 8) * FQP + kc + c];
            a[2] = Qs[r0 * FQP + kc + c + 4];
            a[3] = Qs[(r0 + 8) * FQP + kc + c + 4];
#pragma unroll
            for (int nf = 0; nf < 4; nf++) {
                const int key = wn * 32 + nf * 8 + g;
                uint32_t bf[2];
                bf[0] = Ks[key * FQP + kc + c];
                bf[1] = Ks[key * FQP + kc + c + 4];
                MMA_TF32(acc_s[nf], a, bf);
            }
        }

        // scale + causal mask -> Ss
#pragma unroll
        for (int nf = 0; nf < 4; nf++) {
            const int col = wn * 32 + nf * 8 + c * 2;
            const int kg0 = k0 + col, kg1 = k0 + col + 1;
            const int qg0 = q0 + r0, qg1 = q0 + r0 + 8;
            Ss[r0 * FSP + col]           = (kg0 <= qg0) ? acc_s[nf][0] * scale : NEG_INF;
            Ss[r0 * FSP + col + 1]       = (kg1 <= qg0) ? acc_s[nf][1] * scale : NEG_INF;
            Ss[(r0 + 8) * FSP + col]     = (kg0 <= qg1) ? acc_s[nf][2] * scale : NEG_INF;
            Ss[(r0 + 8) * FSP + col + 1] = (kg1 <= qg1) ? acc_s[nf][3] * scale : NEG_INF;
        }
        __syncthreads();

        // online softmax: 4 threads per row, 16 cols each
        {
            const int r = t >> 2, seg = t & 3;
            float* srow = Ss + r * FSP + seg * 16;
            float mx = NEG_INF;
#pragma unroll
            for (int j = 0; j < 16; j++) mx = fmaxf(mx, srow[j]);
            mx = fmaxf(mx, __shfl_xor_sync(0xffffffffu, mx, 1));
            mx = fmaxf(mx, __shfl_xor_sync(0xffffffffu, mx, 2));
            const float mo = mrow[r];
            const float mnew = fmaxf(mo, mx);
            float sum = 0.f;
#pragma unroll
            for (int j = 0; j < 16; j++) {
                float p = __expf(srow[j] - mnew);
                srow[j] = p;
                sum += p;
            }
            sum += __shfl_xor_sync(0xffffffffu, sum, 1);
            sum += __shfl_xor_sync(0xffffffffu, sum, 2);
            if (seg == 0) {
                const float f = __expf(mo - mnew);
                lrow[r] = lrow[r] * f + sum;
                mrow[r] = mnew;
                frow[r] = f;
            }
        }
        __syncthreads();

        // rescale O
        {
            const float f0 = frow[r0], f1 = frow[r0 + 8];
#pragma unroll
            for (int nf = 0; nf < 8; nf++) {
                acc_o[nf][0] *= f0; acc_o[nf][1] *= f0;
                acc_o[nf][2] *= f1; acc_o[nf][3] *= f1;
            }
        }

        // O += P V : warp: rows [wm*16,+16) x dcols [wn*64,+64)
#pragma unroll
        for (int ks = 0; ks < 8; ks++) {
            const int kk = ks * 8;
            uint32_t p[4];
            p[0] = f2tf32(Ss[r0 * FSP + kk + c]);
            p[1] = f2tf32(Ss[(r0 + 8) * FSP + kk + c]);
            p[2] = f2tf32(Ss[r0 * FSP + kk + c + 4]);
            p[3] = f2tf32(Ss[(r0 + 8) * FSP + kk + c + 4]);
#pragma unroll
            for (int nf = 0; nf < 8; nf++) {
                const int dcol = wn * 64 + nf * 8 + g;
                uint32_t vf[2];
                vf[0] = Vs[(kk + c) * FQP + dcol];
                vf[1] = Vs[(kk + c + 4) * FQP + dcol];
                MMA_TF32(acc_o[nf], p, vf);
            }
        }
    }

    // epilogue
    {
        const float li0 = 1.0f / lrow[r0];
        const float li1 = 1.0f / lrow[r0 + 8];
        float* y0 = y + ((size_t)(b * TT + q0 + r0)) * CC + h * HDD;
        float* y1 = y + ((size_t)(b * TT + q0 + r0 + 8)) * CC + h * HDD;
#pragma unroll
        for (int nf = 0; nf < 8; nf++) {
            const int col = wn * 64 + nf * 8 + c * 2;
            y0[col]     = acc_o[nf][0] * li0;
            y0[col + 1] = acc_o[nf][1] * li0;
            y1[col]     = acc_o[nf][2] * li1;
            y1[col + 1] = acc_o[nf][3] * li1;
        }
    }
}

// ---------------------------------------------------------------------------
// Launch
// ---------------------------------------------------------------------------
extern "C" void kernel_launch(void* const* d_in, const int* in_sizes, int n_in,
                              void* d_out, int out_size)
{
    const float* x      = (const float*)d_in[0];   // [2,2048,2048]
    const float* w_att  = (const float*)d_in[1];   // [6144,2048]
    const float* b_att  = (const float*)d_in[2];   // [6144]
    const float* w_proj = (const float*)d_in[3];   // [2048,2048]
    const float* b_proj = (const float*)d_in[4];   // [2048]
    float* out = (float*)d_out;                    // [2,2048,2048]

    float* qkv = nullptr;
    float* y   = nullptr;
    cudaGetSymbolAddress((void**)&qkv, g_qkv);
    cudaGetSymbolAddress((void**)&y,   g_y);

    cudaFuncSetAttribute(flash_mma_kernel,
                         cudaFuncAttributeMaxDynamicSharedMemorySize,
                         FLASH_SMEM_BYTES);

    // 1) QKV projection: [4096,6144] = x @ w_att^T + b_att
    gemm_mma_kernel<<<dim3(NQKV / 128, MROWS / 128), 256>>>(
        x, w_att, b_att, qkv, MROWS, NQKV, CC);

    // 2) RoPE on q and k sections (in place)
    {
        int total = MROWS * 2048;
        rope_kernel<<<(total + 255) / 256, 256>>>(qkv);
    }

    // 3) Causal flash attention -> y [B,T,C]
    flash_mma_kernel<<<dim3(TT / 64, BB * NHH), 256, FLASH_SMEM_BYTES>>>(qkv, y);

    // 4) Output projection: out = y @ w_proj^T + b_proj
    gemm_mma_kernel<<<dim3(CC / 128, MROWS / 128), 256>>>(
        y, w_proj, b_proj, out, MROWS, CC, CC);
}

// round 4
// speedup vs baseline: 3.0406x; 1.6525x over previous
#include <cuda_runtime.h>
#include <math.h>
#include <stdint.h>

// Problem constants
#define BB     2
#define TT     2048
#define CC     2048
#define NHH    16
#define HDD    128
#define NQKV   6144          // 3*C
#define MROWS  4096          // B*T

// Scratch (device globals; no allocation allowed)
__device__ float g_qkv[(size_t)MROWS * NQKV];       // 96 MB
__device__ float g_y[(size_t)MROWS * CC];           // 32 MB
__device__ float g_xtf[(size_t)MROWS * CC];         // 32 MB (x rounded to tf32)
__device__ float g_watf[(size_t)NQKV * CC];         // 48 MB (w_att rounded)
__device__ float g_wptf[(size_t)CC * CC];           // 16 MB (w_proj rounded)

#define NEG_INF (__int_as_float(0xff800000))

__device__ __forceinline__ uint32_t f2tf32(float x) {
    uint32_t r;
    asm("cvt.rna.tf32.f32 %0, %1;" : "=r"(r) : "f"(x));
    return r;
}

// mma.sync m16n8k8 tf32: D += A*B  (acc in-place)
#define MMA_TF32(d, a, b) \
    asm volatile("mma.sync.aligned.m16n8k8.row.col.f32.tf32.tf32.f32 " \
        "{%0,%1,%2,%3}, {%4,%5,%6,%7}, {%8,%9}, {%0,%1,%2,%3};" \
        : "+f"((d)[0]), "+f"((d)[1]), "+f"((d)[2]), "+f"((d)[3]) \
        : "r"((a)[0]), "r"((a)[1]), "r"((a)[2]), "r"((a)[3]), \
          "r"((b)[0]), "r"((b)[1]))

__device__ __forceinline__ void cp_async16(uint32_t saddr, const void* gptr) {
    asm volatile("cp.async.cg.shared.global [%0], [%1], 16;"
                 :: "r"(saddr), "l"(gptr));
}
#define CP_COMMIT() asm volatile("cp.async.commit_group;" ::: "memory")
#define CP_WAIT(n)  asm volatile("cp.async.wait_group %0;" :: "n"(n) : "memory")

__device__ __forceinline__ uint32_t smem_u32(const void* p) {
    uint32_t a;
    asm("{ .reg .u64 t; cvta.to.shared.u64 t, %1; cvt.u32.u64 %0, t; }"
        : "=r"(a) : "l"(p));
    return a;
}

// ---------------------------------------------------------------------------
// Elementwise tf32 rounding pre-pass (float4-wide)
// ---------------------------------------------------------------------------
__global__ void tf32_round_kernel(const float4* __restrict__ in,
                                  float4* __restrict__ outp, int n4)
{
    int i = blockIdx.x * blockDim.x + threadIdx.x;
    if (i >= n4) return;
    float4 v = in[i];
    float4 o;
    o.x = __uint_as_float(f2tf32(v.x));
    o.y = __uint_as_float(f2tf32(v.y));
    o.z = __uint_as_float(f2tf32(v.z));
    o.w = __uint_as_float(f2tf32(v.w));
    outp[i] = o;
}

// ---------------------------------------------------------------------------
// TF32 tensor-core GEMM with cp.async 3-stage pipeline.
// out[m,n] = sum_k A[m,k]*W[n,k] + bias[n]; A,W pre-rounded to tf32 bits.
// CTA tile 128x128, BK=32, 8 warps (4x2), warp tile 32x64.
// ---------------------------------------------------------------------------
#define GBK 32
#define APITCH 36                        // u32 per row (32 + 4 pad; 144B, 16B-aligned)
#define TILE_U32 (128 * APITCH)          // one operand tile per stage
#define STAGE_U32 (2 * TILE_U32)         // A + B
#define NSTAGE 3
#define GEMM_SMEM_BYTES (NSTAGE * STAGE_U32 * 4)   // 110592

__global__ void __launch_bounds__(256) gemm_cp_kernel(
    const float* __restrict__ A, const float* __restrict__ W,
    const float* __restrict__ bias, float* __restrict__ out,
    int M, int N, int K)
{
    extern __shared__ __align__(16) uint32_t gsm[];
    const uint32_t sbase = smem_u32(gsm);

    const int t = threadIdx.x, lane = t & 31, wid = t >> 5;
    const int wm = wid & 3, wn = wid >> 2;
    const int g = lane >> 2, c = lane & 3;
    const int m0 = blockIdx.y * 128, n0 = blockIdx.x * 128;

    // loader mapping: 1024 16B-chunks per operand tile, 4 per thread
    const int lrow = t >> 3;             // 0..31 (plus i*32)
    const int lcc  = (t & 7) * 4;        // u32 col 0,4,...,28

    const float* Ab = A + (size_t)m0 * K;
    const float* Wb = W + (size_t)n0 * K;

    float acc[2][8][4];
#pragma unroll
    for (int i = 0; i < 2; i++)
#pragma unroll
        for (int j = 0; j < 8; j++)
#pragma unroll
            for (int r = 0; r < 4; r++) acc[i][j][r] = 0.f;

    const int nsteps = K >> 5;

    // issue a stage's loads
    auto issue_stage = [&](int s, int kk) {
        const uint32_t sA = sbase + (uint32_t)(s * STAGE_U32) * 4;
        const uint32_t sB = sA + TILE_U32 * 4;
        const int kof = kk * GBK + lcc;
#pragma unroll
        for (int i = 0; i < 4; i++) {
            const int row = lrow + i * 32;
            cp_async16(sA + (row * APITCH + lcc) * 4, Ab + (size_t)row * K + kof);
            cp_async16(sB + (row * APITCH + lcc) * 4, Wb + (size_t)row * K + kof);
        }
        CP_COMMIT();
    };

    issue_stage(0, 0);
    issue_stage(1, 1);

    for (int j = 0; j < nsteps; j++) {
        const int cur = j % NSTAGE;
        CP_WAIT(1);
        __syncthreads();
        if (j + 2 < nsteps) issue_stage((j + 2) % NSTAGE, j + 2);

        const uint32_t* sA = gsm + cur * STAGE_U32;
        const uint32_t* sB = sA + TILE_U32;
#pragma unroll
        for (int ks = 0; ks < 4; ks++) {
            const int kc = ks * 8;
            uint32_t a[2][4];
#pragma unroll
            for (int mt = 0; mt < 2; mt++) {
                const int row = wm * 32 + mt * 16 + g;
                a[mt][0] = sA[row * APITCH + kc + c];
                a[mt][1] = sA[(row + 8) * APITCH + kc + c];
                a[mt][2] = sA[row * APITCH + kc + c + 4];
                a[mt][3] = sA[(row + 8) * APITCH + kc + c + 4];
            }
            uint32_t bfr[8][2];
#pragma unroll
            for (int nf = 0; nf < 8; nf++) {
                const int col = wn * 64 + nf * 8 + g;
                bfr[nf][0] = sB[col * APITCH + kc + c];
                bfr[nf][1] = sB[col * APITCH + kc + c + 4];
            }
#pragma unroll
            for (int mt = 0; mt < 2; mt++)
#pragma unroll
                for (int nf = 0; nf < 8; nf++)
                    MMA_TF32(acc[mt][nf], a[mt], bfr[nf]);
        }
        __syncthreads();
    }

    // epilogue
#pragma unroll
    for (int mt = 0; mt < 2; mt++) {
        const int r0 = m0 + wm * 32 + mt * 16 + g;
#pragma unroll
        for (int nf = 0; nf < 8; nf++) {
            const int col = n0 + wn * 64 + nf * 8 + c * 2;
            const float b0v = bias[col], b1v = bias[col + 1];
            float* o0 = out + (size_t)r0 * N + col;
            float* o1 = out + (size_t)(r0 + 8) * N + col;
            o0[0] = acc[mt][nf][0] + b0v;
            o0[1] = acc[mt][nf][1] + b1v;
            o1[0] = acc[mt][nf][2] + b0v;
            o1[1] = acc[mt][nf][3] + b1v;
        }
    }
}

// ---------------------------------------------------------------------------
// RoPE applied in-place to the q and k sections of qkv [MROWS, 6144].
// ---------------------------------------------------------------------------
__global__ void rope_kernel(float* __restrict__ qkv)
{
    int idx = blockIdx.x * blockDim.x + threadIdx.x;   // one pair per thread
    if (idx >= MROWS * 2048) return;
    int row = idx >> 11;
    int p   = idx & 2047;
    int tpos = row & (TT - 1);

    int col = (p < 1024) ? (2 * p) : (2048 + 2 * (p - 1024));
    int d   = col & (HDD - 1);
    int i   = d >> 1;

    float theta = 1.0f / powf(10000.0f, (float)i / 64.0f);
    float ang   = (float)tpos * theta;
    float cs = cosf(ang);
    float sn = sinf(ang);

    float2* ptr = (float2*)(qkv + (size_t)row * NQKV + col);
    float2 v = *ptr;
    float2 o;
    o.x = v.x * cs - v.y * sn;
    o.y = v.x * sn + v.y * cs;
    *ptr = o;
}

// ---------------------------------------------------------------------------
// Flash attention with tf32 mma.sync. One block per (b,h,qtile of 64).
// ---------------------------------------------------------------------------
#define FQP 132   // u32 pitch for Qs/Ks/Vs rows (128 + 4)
#define FSP 68    // float pitch for score tile
#define FLASH_SMEM_U32 (3 * 64 * FQP + 64 * FSP + 3 * 64)
#define FLASH_SMEM_BYTES (FLASH_SMEM_U32 * 4)

__global__ void __launch_bounds__(256) flash_mma_kernel(
    const float* __restrict__ qkv, float* __restrict__ y)
{
    extern __shared__ uint32_t fsm[];
    uint32_t* Qs = fsm;                    // [64][FQP] tf32
    uint32_t* Ks = Qs + 64 * FQP;          // [64][FQP] tf32
    uint32_t* Vs = Ks + 64 * FQP;          // [64][FQP] tf32
    float*    Ss = (float*)(Vs + 64 * FQP);// [64][FSP]
    float* mrow = Ss + 64 * FSP;
    float* lrow = mrow + 64;
    float* frow = lrow + 64;

    const int bh = blockIdx.y, b = bh >> 4, h = bh & 15;
    const int qt = blockIdx.x, q0 = qt * 64;
    const int t = threadIdx.x, lane = t & 31, wid = t >> 5;
    const int wm = wid & 3, wn = wid >> 2;
    const int g = lane >> 2, c = lane & 3;
    const float scale = 0.08838834764831845f;   // 1/sqrt(128)

    // load Q tile [64][128] -> tf32 smem
    const float* Qg = qkv + ((size_t)(b * TT + q0)) * NQKV + h * HDD;
    {
        const int r = wid * 8;
#pragma unroll
        for (int i = 0; i < 8; i++) {
            float4 v = *(const float4*)(Qg + (size_t)(r + i) * NQKV + lane * 4);
            uint4 u;
            u.x = f2tf32(v.x); u.y = f2tf32(v.y); u.z = f2tf32(v.z); u.w = f2tf32(v.w);
            *(uint4*)(Qs + (r + i) * FQP + lane * 4) = u;
        }
    }
    if (t < 64) { mrow[t] = NEG_INF; lrow[t] = 0.f; }

    const int r0 = wm * 16 + g;

    float acc_o[8][4];
#pragma unroll
    for (int j = 0; j < 8; j++)
#pragma unroll
        for (int r = 0; r < 4; r++) acc_o[j][r] = 0.f;

    for (int kt = 0; kt <= qt; kt++) {
        const int k0 = kt * 64;
        const float* Kg = qkv + ((size_t)(b * TT + k0)) * NQKV + CC + h * HDD;
        const float* Vg = Kg + CC;

        __syncthreads();
        {
            const int r = wid * 8;
#pragma unroll
            for (int i = 0; i < 8; i++) {
                float4 kv = *(const float4*)(Kg + (size_t)(r + i) * NQKV + lane * 4);
                uint4 u;
                u.x = f2tf32(kv.x); u.y = f2tf32(kv.y); u.z = f2tf32(kv.z); u.w = f2tf32(kv.w);
                *(uint4*)(Ks + (r + i) * FQP + lane * 4) = u;
                float4 vv = *(const float4*)(Vg + (size_t)(r + i) * NQKV + lane * 4);
                u.x = f2tf32(vv.x); u.y = f2tf32(vv.y); u.z = f2tf32(vv.z); u.w = f2tf32(vv.w);
                *(uint4*)(Vs + (r + i) * FQP + lane * 4) = u;
            }
        }
        __syncthreads();

        float acc_s[4][4];
#pragma unroll
        for (int j = 0; j < 4; j++)
#pragma unroll
            for (int r = 0; r < 4; r++) acc_s[j][r] = 0.f;

#pragma unroll
        for (int ks = 0; ks < 16; ks++) {
            const int kc = ks * 8;
            uint32_t a[4];
            a[0] = Qs[r0 * FQP + kc + c];
            a[1] = Qs[(r0 + 8) * FQP + kc + c];
            a[2] = Qs[r0 * FQP + kc + c + 4];
            a[3] = Qs[(r0 + 8) * FQP + kc + c + 4];
#pragma unroll
            for (int nf = 0; nf < 4; nf++) {
                const int key = wn * 32 + nf * 8 + g;
                uint32_t bf[2];
                bf[0] = Ks[key * FQP + kc + c];
                bf[1] = Ks[key * FQP + kc + c + 4];
                MMA_TF32(acc_s[nf], a, bf);
            }
        }

#pragma unroll
        for (int nf = 0; nf < 4; nf++) {
            const int col = wn * 32 + nf * 8 + c * 2;
            const int kg0 = k0 + col, kg1 = k0 + col + 1;
            const int qg0 = q0 + r0, qg1 = q0 + r0 + 8;
            Ss[r0 * FSP + col]           = (kg0 <= qg0) ? acc_s[nf][0] * scale : NEG_INF;
            Ss[r0 * FSP + col + 1]       = (kg1 <= qg0) ? acc_s[nf][1] * scale : NEG_INF;
            Ss[(r0 + 8) * FSP + col]     = (kg0 <= qg1) ? acc_s[nf][2] * scale : NEG_INF;
            Ss[(r0 + 8) * FSP + col + 1] = (kg1 <= qg1) ? acc_s[nf][3] * scale : NEG_INF;
        }
        __syncthreads();

        {
            const int r = t >> 2, seg = t & 3;
            float* srow = Ss + r * FSP + seg * 16;
            float mx = NEG_INF;
#pragma unroll
            for (int j = 0; j < 16; j++) mx = fmaxf(mx, srow[j]);
            mx = fmaxf(mx, __shfl_xor_sync(0xffffffffu, mx, 1));
            mx = fmaxf(mx, __shfl_xor_sync(0xffffffffu, mx, 2));
            const float mo = mrow[r];
            const float mnew = fmaxf(mo, mx);
            float sum = 0.f;
#pragma unroll
            for (int j = 0; j < 16; j++) {
                float p = __expf(srow[j] - mnew);
                srow[j] = p;
                sum += p;
            }
            sum += __shfl_xor_sync(0xffffffffu, sum, 1);
            sum += __shfl_xor_sync(0xffffffffu, sum, 2);
            if (seg == 0) {
                const float f = __expf(mo - mnew);
                lrow[r] = lrow[r] * f + sum;
                mrow[r] = mnew;
                frow[r] = f;
            }
        }
        __syncthreads();

        {
            const float f0 = frow[r0], f1 = frow[r0 + 8];
#pragma unroll
            for (int nf = 0; nf < 8; nf++) {
                acc_o[nf][0] *= f0; acc_o[nf][1] *= f0;
                acc_o[nf][2] *= f1; acc_o[nf][3] *= f1;
            }
        }

#pragma unroll
        for (int ks = 0; ks < 8; ks++) {
            const int kk = ks * 8;
            uint32_t p[4];
            p[0] = f2tf32(Ss[r0 * FSP + kk + c]);
            p[1] = f2tf32(Ss[(r0 + 8) * FSP + kk + c]);
            p[2] = f2tf32(Ss[r0 * FSP + kk + c + 4]);
            p[3] = f2tf32(Ss[(r0 + 8) * FSP + kk + c + 4]);
#pragma unroll
            for (int nf = 0; nf < 8; nf++) {
                const int dcol = wn * 64 + nf * 8 + g;
                uint32_t vf[2];
                vf[0] = Vs[(kk + c) * FQP + dcol];
                vf[1] = Vs[(kk + c + 4) * FQP + dcol];
                MMA_TF32(acc_o[nf], p, vf);
            }
        }
    }

    // epilogue: divide by l, round to tf32 (y feeds proj GEMM as A operand)
    {
        const float li0 = 1.0f / lrow[r0];
        const float li1 = 1.0f / lrow[r0 + 8];
        float* y0 = y + ((size_t)(b * TT + q0 + r0)) * CC + h * HDD;
        float* y1 = y + ((size_t)(b * TT + q0 + r0 + 8)) * CC + h * HDD;
#pragma unroll
        for (int nf = 0; nf < 8; nf++) {
            const int col = wn * 64 + nf * 8 + c * 2;
            y0[col]     = __uint_as_float(f2tf32(acc_o[nf][0] * li0));
            y0[col + 1] = __uint_as_float(f2tf32(acc_o[nf][1] * li0));
            y1[col]     = __uint_as_float(f2tf32(acc_o[nf][2] * li1));
            y1[col + 1] = __uint_as_float(f2tf32(acc_o[nf][3] * li1));
        }
    }
}

// ---------------------------------------------------------------------------
// Launch
// ---------------------------------------------------------------------------
extern "C" void kernel_launch(void* const* d_in, const int* in_sizes, int n_in,
                              void* d_out, int out_size)
{
    const float* x      = (const float*)d_in[0];   // [2,2048,2048]
    const float* w_att  = (const float*)d_in[1];   // [6144,2048]
    const float* b_att  = (const float*)d_in[2];   // [6144]
    const float* w_proj = (const float*)d_in[3];   // [2048,2048]
    const float* b_proj = (const float*)d_in[4];   // [2048]
    float* out = (float*)d_out;                    // [2,2048,2048]

    float *qkv, *y, *xtf, *watf, *wptf;
    cudaGetSymbolAddress((void**)&qkv,  g_qkv);
    cudaGetSymbolAddress((void**)&y,    g_y);
    cudaGetSymbolAddress((void**)&xtf,  g_xtf);
    cudaGetSymbolAddress((void**)&watf, g_watf);
    cudaGetSymbolAddress((void**)&wptf, g_wptf);

    cudaFuncSetAttribute(gemm_cp_kernel,
                         cudaFuncAttributeMaxDynamicSharedMemorySize,
                         GEMM_SMEM_BYTES);
    cudaFuncSetAttribute(flash_mma_kernel,
                         cudaFuncAttributeMaxDynamicSharedMemorySize,
                         FLASH_SMEM_BYTES);

    // 0) Pre-round inputs to tf32
    {
        int n4;
        n4 = (MROWS * CC) / 4;
        tf32_round_kernel<<<(n4 + 255) / 256, 256>>>((const float4*)x, (float4*)xtf, n4);
        n4 = (NQKV * CC) / 4;
        tf32_round_kernel<<<(n4 + 255) / 256, 256>>>((const float4*)w_att, (float4*)watf, n4);
        n4 = (CC * CC) / 4;
        tf32_round_kernel<<<(n4 + 255) / 256, 256>>>((const float4*)w_proj, (float4*)wptf, n4);
    }

    // 1) QKV projection: [4096,6144] = x @ w_att^T + b_att
    gemm_cp_kernel<<<dim3(NQKV / 128, MROWS / 128), 256, GEMM_SMEM_BYTES>>>(
        xtf, watf, b_att, qkv, MROWS, NQKV, CC);

    // 2) RoPE on q and k sections (in place)
    {
        int total = MROWS * 2048;
        rope_kernel<<<(total + 255) / 256, 256>>>(qkv);
    }

    // 3) Causal flash attention -> y [B,T,C] (tf32-rounded)
    flash_mma_kernel<<<dim3(TT / 64, BB * NHH), 256, FLASH_SMEM_BYTES>>>(qkv, y);

    // 4) Output projection: out = y @ w_proj^T + b_proj
    gemm_cp_kernel<<<dim3(CC / 128, MROWS / 128), 256, GEMM_SMEM_BYTES>>>(
        y, wptf, b_proj, out, MROWS, CC, CC);
}

// round 5
// speedup vs baseline: 3.2129x; 1.0567x over previous
#include <cuda_runtime.h>
#include <math.h>
#include <stdint.h>

// Problem constants
#define BB     2
#define TT     2048
#define CC     2048
#define NHH    16
#define HDD    128
#define NQKV   6144          // 3*C
#define MROWS  4096          // B*T

// Scratch (device globals; no allocation allowed)
__device__ float g_qkv[(size_t)MROWS * NQKV];       // 96 MB
__device__ float g_y[(size_t)MROWS * CC];           // 32 MB
__device__ float g_xtf[(size_t)MROWS * CC];         // 32 MB (x rounded to tf32)
__device__ float g_watf[(size_t)NQKV * CC];         // 48 MB (w_att rounded)
__device__ float g_wptf[(size_t)CC * CC];           // 16 MB (w_proj rounded)

#define NEG_INF (__int_as_float(0xff800000))

__device__ __forceinline__ uint32_t f2tf32(float x) {
    uint32_t r;
    asm("cvt.rna.tf32.f32 %0, %1;" : "=r"(r) : "f"(x));
    return r;
}

// mma.sync m16n8k8 tf32: D += A*B  (acc in-place)
#define MMA_TF32(d, a, b) \
    asm volatile("mma.sync.aligned.m16n8k8.row.col.f32.tf32.tf32.f32 " \
        "{%0,%1,%2,%3}, {%4,%5,%6,%7}, {%8,%9}, {%0,%1,%2,%3};" \
        : "+f"((d)[0]), "+f"((d)[1]), "+f"((d)[2]), "+f"((d)[3]) \
        : "r"((a)[0]), "r"((a)[1]), "r"((a)[2]), "r"((a)[3]), \
          "r"((b)[0]), "r"((b)[1]))

__device__ __forceinline__ void cp_async16(uint32_t saddr, const void* gptr) {
    asm volatile("cp.async.cg.shared.global [%0], [%1], 16;"
                 :: "r"(saddr), "l"(gptr));
}
#define CP_COMMIT() asm volatile("cp.async.commit_group;" ::: "memory")
#define CP_WAIT(n)  asm volatile("cp.async.wait_group %0;" :: "n"(n) : "memory")

__device__ __forceinline__ uint32_t smem_u32(const void* p) {
    uint32_t a;
    asm("{ .reg .u64 t; cvta.to.shared.u64 t, %1; cvt.u32.u64 %0, t; }"
        : "=r"(a) : "l"(p));
    return a;
}

// ---------------------------------------------------------------------------
// Elementwise tf32 rounding pre-pass (float4-wide)
// ---------------------------------------------------------------------------
__global__ void tf32_round_kernel(const float4* __restrict__ in,
                                  float4* __restrict__ outp, int n4)
{
    int i = blockIdx.x * blockDim.x + threadIdx.x;
    if (i >= n4) return;
    float4 v = in[i];
    float4 o;
    o.x = __uint_as_float(f2tf32(v.x));
    o.y = __uint_as_float(f2tf32(v.y));
    o.z = __uint_as_float(f2tf32(v.z));
    o.w = __uint_as_float(f2tf32(v.w));
    outp[i] = o;
}

// ---------------------------------------------------------------------------
// TF32 tensor-core GEMM, cp.async 3-stage, CTA tile 128x256, warp tile 64x64.
// out[m,n] = sum_k A[m,k]*W[n,k] + bias[n]; A,W pre-rounded to tf32 bits.
// 8 warps arranged 2 (M) x 4 (N). BK=32.
// ---------------------------------------------------------------------------
#define GBK 32
#define APITCH 36                         // u32 per row (32 + 4 pad)
#define A_TILE_U32 (128 * APITCH)
#define B_TILE_U32 (256 * APITCH)
#define STAGE_U32 (A_TILE_U32 + B_TILE_U32)
#define NSTAGE 3
#define GEMM_SMEM_BYTES (NSTAGE * STAGE_U32 * 4)   // 165888

__global__ void __launch_bounds__(256, 1) gemm_cp_kernel(
    const float* __restrict__ A, const float* __restrict__ W,
    const float* __restrict__ bias, float* __restrict__ out,
    int M, int N, int K)
{
    extern __shared__ __align__(16) uint32_t gsm[];
    const uint32_t sbase = smem_u32(gsm);

    const int t = threadIdx.x, lane = t & 31, wid = t >> 5;
    const int wm = wid & 1, wn = wid >> 1;      // 2 x 4 warp grid
    const int g = lane >> 2, c = lane & 3;
    const int m0 = blockIdx.y * 128, n0 = blockIdx.x * 256;

    const int lrow = t >> 3;             // 0..31
    const int lcc  = (t & 7) * 4;        // u32 col 0,4,...,28

    const float* Ab = A + (size_t)m0 * K;
    const float* Wb = W + (size_t)n0 * K;

    float acc[4][8][4];
#pragma unroll
    for (int i = 0; i < 4; i++)
#pragma unroll
        for (int j = 0; j < 8; j++)
#pragma unroll
            for (int r = 0; r < 4; r++) acc[i][j][r] = 0.f;

    const int nsteps = K >> 5;

    auto issue_stage = [&](int s, int kk) {
        const uint32_t sA = sbase + (uint32_t)(s * STAGE_U32) * 4;
        const uint32_t sB = sA + A_TILE_U32 * 4;
        const int kof = kk * GBK + lcc;
#pragma unroll
        for (int i = 0; i < 4; i++) {           // A: 128 rows
            const int row = lrow + i * 32;
            cp_async16(sA + (row * APITCH + lcc) * 4, Ab + (size_t)row * K + kof);
        }
#pragma unroll
        for (int i = 0; i < 8; i++) {           // B: 256 rows
            const int row = lrow + i * 32;
            cp_async16(sB + (row * APITCH + lcc) * 4, Wb + (size_t)row * K + kof);
        }
        CP_COMMIT();
    };

    issue_stage(0, 0);
    issue_stage(1, 1);

    for (int j = 0; j < nsteps; j++) {
        const int cur = j % NSTAGE;
        CP_WAIT(1);
        __syncthreads();    // stage j arrived; all warps done with stage j-1
        if (j + 2 < nsteps) issue_stage((j + 2) % NSTAGE, j + 2);

        const uint32_t* sA = gsm + cur * STAGE_U32;
        const uint32_t* sB = sA + A_TILE_U32;
#pragma unroll
        for (int ks = 0; ks < 4; ks++) {
            const int kc = ks * 8;
            uint32_t a[4][4];
#pragma unroll
            for (int mt = 0; mt < 4; mt++) {
                const int row = wm * 64 + mt * 16 + g;
                a[mt][0] = sA[row * APITCH + kc + c];
                a[mt][1] = sA[(row + 8) * APITCH + kc + c];
                a[mt][2] = sA[row * APITCH + kc + c + 4];
                a[mt][3] = sA[(row + 8) * APITCH + kc + c + 4];
            }
            uint32_t bfr[8][2];
#pragma unroll
            for (int nf = 0; nf < 8; nf++) {
                const int col = wn * 64 + nf * 8 + g;
                bfr[nf][0] = sB[col * APITCH + kc + c];
                bfr[nf][1] = sB[col * APITCH + kc + c + 4];
            }
#pragma unroll
            for (int mt = 0; mt < 4; mt++)
#pragma unroll
                for (int nf = 0; nf < 8; nf++)
                    MMA_TF32(acc[mt][nf], a[mt], bfr[nf]);
        }
    }

    __syncthreads();

    // epilogue
#pragma unroll
    for (int mt = 0; mt < 4; mt++) {
        const int r0 = m0 + wm * 64 + mt * 16 + g;
#pragma unroll
        for (int nf = 0; nf < 8; nf++) {
            const int col = n0 + wn * 64 + nf * 8 + c * 2;
            const float b0v = bias[col], b1v = bias[col + 1];
            float* o0 = out + (size_t)r0 * N + col;
            float* o1 = out + (size_t)(r0 + 8) * N + col;
            o0[0] = acc[mt][nf][0] + b0v;
            o0[1] = acc[mt][nf][1] + b1v;
            o1[0] = acc[mt][nf][2] + b0v;
            o1[1] = acc[mt][nf][3] + b1v;
        }
    }
}

// ---------------------------------------------------------------------------
// RoPE applied in-place to the q and k sections of qkv [MROWS, 6144].
// ---------------------------------------------------------------------------
__global__ void rope_kernel(float* __restrict__ qkv)
{
    int idx = blockIdx.x * blockDim.x + threadIdx.x;   // one pair per thread
    if (idx >= MROWS * 2048) return;
    int row = idx >> 11;
    int p   = idx & 2047;
    int tpos = row & (TT - 1);

    int col = (p < 1024) ? (2 * p) : (2048 + 2 * (p - 1024));
    int d   = col & (HDD - 1);
    int i   = d >> 1;

    float theta = 1.0f / powf(10000.0f, (float)i / 64.0f);
    float ang   = (float)tpos * theta;
    float cs = cosf(ang);
    float sn = sinf(ang);

    float2* ptr = (float2*)(qkv + (size_t)row * NQKV + col);
    float2 v = *ptr;
    float2 o;
    o.x = v.x * cs - v.y * sn;
    o.y = v.x * sn + v.y * cs;
    *ptr = o;
}

// ---------------------------------------------------------------------------
// Flash attention with tf32 mma.sync. One block per (b,h,qtile of 64).
// ---------------------------------------------------------------------------
#define FQP 132   // u32 pitch for Qs/Ks/Vs rows (128 + 4)
#define FSP 68    // float pitch for score tile
#define FLASH_SMEM_U32 (3 * 64 * FQP + 64 * FSP + 3 * 64)
#define FLASH_SMEM_BYTES (FLASH_SMEM_U32 * 4)

__global__ void __launch_bounds__(256) flash_mma_kernel(
    const float* __restrict__ qkv, float* __restrict__ y)
{
    extern __shared__ uint32_t fsm[];
    uint32_t* Qs = fsm;                    // [64][FQP] tf32
    uint32_t* Ks = Qs + 64 * FQP;          // [64][FQP] tf32
    uint32_t* Vs = Ks + 64 * FQP;          // [64][FQP] tf32
    float*    Ss = (float*)(Vs + 64 * FQP);// [64][FSP]
    float* mrow = Ss + 64 * FSP;
    float* lrow = mrow + 64;
    float* frow = lrow + 64;

    const int bh = blockIdx.y, b = bh >> 4, h = bh & 15;
    const int qt = blockIdx.x, q0 = qt * 64;
    const int t = threadIdx.x, lane = t & 31, wid = t >> 5;
    const int wm = wid & 3, wn = wid >> 2;
    const int g = lane >> 2, c = lane & 3;
    const float scale = 0.08838834764831845f;   // 1/sqrt(128)

    const float* Qg = qkv + ((size_t)(b * TT + q0)) * NQKV + h * HDD;
    {
        const int r = wid * 8;
#pragma unroll
        for (int i = 0; i < 8; i++) {
            float4 v = *(const float4*)(Qg + (size_t)(r + i) * NQKV + lane * 4);
            uint4 u;
            u.x = f2tf32(v.x); u.y = f2tf32(v.y); u.z = f2tf32(v.z); u.w = f2tf32(v.w);
            *(uint4*)(Qs + (r + i) * FQP + lane * 4) = u;
        }
    }
    if (t < 64) { mrow[t] = NEG_INF; lrow[t] = 0.f; }

    const int r0 = wm * 16 + g;

    float acc_o[8][4];
#pragma unroll
    for (int j = 0; j < 8; j++)
#pragma unroll
        for (int r = 0; r < 4; r++) acc_o[j][r] = 0.f;

    for (int kt = 0; kt <= qt; kt++) {
        const int k0 = kt * 64;
        const float* Kg = qkv + ((size_t)(b * TT + k0)) * NQKV + CC + h * HDD;
        const float* Vg = Kg + CC;

        __syncthreads();
        {
            const int r = wid * 8;
#pragma unroll
            for (int i = 0; i < 8; i++) {
                float4 kv = *(const float4*)(Kg + (size_t)(r + i) * NQKV + lane * 4);
                uint4 u;
                u.x = f2tf32(kv.x); u.y = f2tf32(kv.y); u.z = f2tf32(kv.z); u.w = f2tf32(kv.w);
                *(uint4*)(Ks + (r + i) * FQP + lane * 4) = u;
                float4 vv = *(const float4*)(Vg + (size_t)(r + i) * NQKV + lane * 4);
                u.x = f2tf32(vv.x); u.y = f2tf32(vv.y); u.z = f2tf32(vv.z); u.w = f2tf32(vv.w);
                *(uint4*)(Vs + (r + i) * FQP + lane * 4) = u;
            }
        }
        __syncthreads();

        float acc_s[4][4];
#pragma unroll
        for (int j = 0; j < 4; j++)
#pragma unroll
            for (int r = 0; r < 4; r++) acc_s[j][r] = 0.f;

#pragma unroll
        for (int ks = 0; ks < 16; ks++) {
            const int kc = ks * 8;
            uint32_t a[4];
            a[0] = Qs[r0 * FQP + kc + c];
            a[1] = Qs[(r0 + 8) * FQP + kc + c];
            a[2] = Qs[r0 * FQP + kc + c + 4];
            a[3] = Qs[(r0 + 8) * FQP + kc + c + 4];
#pragma unroll
            for (int nf = 0; nf < 4; nf++) {
                const int key = wn * 32 + nf * 8 + g;
                uint32_t bf[2];
                bf[0] = Ks[key * FQP + kc + c];
                bf[1] = Ks[key * FQP + kc + c + 4];
                MMA_TF32(acc_s[nf], a, bf);
            }
        }

#pragma unroll
        for (int nf = 0; nf < 4; nf++) {
            const int col = wn * 32 + nf * 8 + c * 2;
            const int kg0 = k0 + col, kg1 = k0 + col + 1;
            const int qg0 = q0 + r0, qg1 = q0 + r0 + 8;
            Ss[r0 * FSP + col]           = (kg0 <= qg0) ? acc_s[nf][0] * scale : NEG_INF;
            Ss[r0 * FSP + col + 1]       = (kg1 <= qg0) ? acc_s[nf][1] * scale : NEG_INF;
            Ss[(r0 + 8) * FSP + col]     = (kg0 <= qg1) ? acc_s[nf][2] * scale : NEG_INF;
            Ss[(r0 + 8) * FSP + col + 1] = (kg1 <= qg1) ? acc_s[nf][3] * scale : NEG_INF;
        }
        __syncthreads();

        {
            const int r = t >> 2, seg = t & 3;
            float* srow = Ss + r * FSP + seg * 16;
            float mx = NEG_INF;
#pragma unroll
            for (int j = 0; j < 16; j++) mx = fmaxf(mx, srow[j]);
            mx = fmaxf(mx, __shfl_xor_sync(0xffffffffu, mx, 1));
            mx = fmaxf(mx, __shfl_xor_sync(0xffffffffu, mx, 2));
            const float mo = mrow[r];
            const float mnew = fmaxf(mo, mx);
            float sum = 0.f;
#pragma unroll
            for (int j = 0; j < 16; j++) {
                float p = __expf(srow[j] - mnew);
                srow[j] = p;
                sum += p;
            }
            sum += __shfl_xor_sync(0xffffffffu, sum, 1);
            sum += __shfl_xor_sync(0xffffffffu, sum, 2);
            if (seg == 0) {
                const float f = __expf(mo - mnew);
                lrow[r] = lrow[r] * f + sum;
                mrow[r] = mnew;
                frow[r] = f;
            }
        }
        __syncthreads();

        {
            const float f0 = frow[r0], f1 = frow[r0 + 8];
#pragma unroll
            for (int nf = 0; nf < 8; nf++) {
                acc_o[nf][0] *= f0; acc_o[nf][1] *= f0;
                acc_o[nf][2] *= f1; acc_o[nf][3] *= f1;
            }
        }

#pragma unroll
        for (int ks = 0; ks < 8; ks++) {
            const int kk = ks * 8;
            uint32_t p[4];
            p[0] = f2tf32(Ss[r0 * FSP + kk + c]);
            p[1] = f2tf32(Ss[(r0 + 8) * FSP + kk + c]);
            p[2] = f2tf32(Ss[r0 * FSP + kk + c + 4]);
            p[3] = f2tf32(Ss[(r0 + 8) * FSP + kk + c + 4]);
#pragma unroll
            for (int nf = 0; nf < 8; nf++) {
                const int dcol = wn * 64 + nf * 8 + g;
                uint32_t vf[2];
                vf[0] = Vs[(kk + c) * FQP + dcol];
                vf[1] = Vs[(kk + c + 4) * FQP + dcol];
                MMA_TF32(acc_o[nf], p, vf);
            }
        }
    }

    // epilogue: divide by l, round to tf32 (y feeds proj GEMM as A operand)
    {
        const float li0 = 1.0f / lrow[r0];
        const float li1 = 1.0f / lrow[r0 + 8];
        float* y0 = y + ((size_t)(b * TT + q0 + r0)) * CC + h * HDD;
        float* y1 = y + ((size_t)(b * TT + q0 + r0 + 8)) * CC + h * HDD;
#pragma unroll
        for (int nf = 0; nf < 8; nf++) {
            const int col = wn * 64 + nf * 8 + c * 2;
            y0[col]     = __uint_as_float(f2tf32(acc_o[nf][0] * li0));
            y0[col + 1] = __uint_as_float(f2tf32(acc_o[nf][1] * li0));
            y1[col]     = __uint_as_float(f2tf32(acc_o[nf][2] * li1));
            y1[col + 1] = __uint_as_float(f2tf32(acc_o[nf][3] * li1));
        }
    }
}

// ---------------------------------------------------------------------------
// Launch
// ---------------------------------------------------------------------------
extern "C" void kernel_launch(void* const* d_in, const int* in_sizes, int n_in,
                              void* d_out, int out_size)
{
    const float* x      = (const float*)d_in[0];   // [2,2048,2048]
    const float* w_att  = (const float*)d_in[1];   // [6144,2048]
    const float* b_att  = (const float*)d_in[2];   // [6144]
    const float* w_proj = (const float*)d_in[3];   // [2048,2048]
    const float* b_proj = (const float*)d_in[4];   // [2048]
    float* out = (float*)d_out;                    // [2,2048,2048]

    float *qkv, *y, *xtf, *watf, *wptf;
    cudaGetSymbolAddress((void**)&qkv,  g_qkv);
    cudaGetSymbolAddress((void**)&y,    g_y);
    cudaGetSymbolAddress((void**)&xtf,  g_xtf);
    cudaGetSymbolAddress((void**)&watf, g_watf);
    cudaGetSymbolAddress((void**)&wptf, g_wptf);

    cudaFuncSetAttribute(gemm_cp_kernel,
                         cudaFuncAttributeMaxDynamicSharedMemorySize,
                         GEMM_SMEM_BYTES);
    cudaFuncSetAttribute(flash_mma_kernel,
                         cudaFuncAttributeMaxDynamicSharedMemorySize,
                         FLASH_SMEM_BYTES);

    // 0) Pre-round inputs to tf32
    {
        int n4;
        n4 = (MROWS * CC) / 4;
        tf32_round_kernel<<<(n4 + 255) / 256, 256>>>((const float4*)x, (float4*)xtf, n4);
        n4 = (NQKV * CC) / 4;
        tf32_round_kernel<<<(n4 + 255) / 256, 256>>>((const float4*)w_att, (float4*)watf, n4);
        n4 = (CC * CC) / 4;
        tf32_round_kernel<<<(n4 + 255) / 256, 256>>>((const float4*)w_proj, (float4*)wptf, n4);
    }

    // 1) QKV projection: [4096,6144] = x @ w_att^T + b_att
    gemm_cp_kernel<<<dim3(NQKV / 256, MROWS / 128), 256, GEMM_SMEM_BYTES>>>(
        xtf, watf, b_att, qkv, MROWS, NQKV, CC);

    // 2) RoPE on q and k sections (in place)
    {
        int total = MROWS * 2048;
        rope_kernel<<<(total + 255) / 256, 256>>>(qkv);
    }

    // 3) Causal flash attention -> y [B,T,C] (tf32-rounded)
    flash_mma_kernel<<<dim3(TT / 64, BB * NHH), 256, FLASH_SMEM_BYTES>>>(qkv, y);

    // 4) Output projection: out = y @ w_proj^T + b_proj
    gemm_cp_kernel<<<dim3(CC / 256, MROWS / 128), 256, GEMM_SMEM_BYTES>>>(
        y, wptf, b_proj, out, MROWS, CC, CC);
}

// round 6
// speedup vs baseline: 3.2769x; 1.0199x over previous
#include <cuda_runtime.h>
#include <math.h>
#include <stdint.h>

// Problem constants
#define BB     2
#define TT     2048
#define CC     2048
#define NHH    16
#define HDD    128
#define NQKV   6144          // 3*C
#define MROWS  4096          // B*T

// Scratch (device globals; no allocation allowed)
__device__ float g_qkv[(size_t)MROWS * NQKV];       // 96 MB
__device__ float g_y[(size_t)MROWS * CC];           // 32 MB
__device__ float g_xtf[(size_t)MROWS * CC];         // 32 MB (x rounded to tf32)
__device__ float g_watf[(size_t)NQKV * CC];         // 48 MB (w_att rounded)
__device__ float g_wptf[(size_t)CC * CC];           // 16 MB (w_proj rounded)
__device__ float2 g_rope[TT * 64];                  // cos/sin table [t][i]

#define NEG_INF (__int_as_float(0xff800000))

__device__ __forceinline__ uint32_t f2tf32(float x) {
    uint32_t r;
    asm("cvt.rna.tf32.f32 %0, %1;" : "=r"(r) : "f"(x));
    return r;
}

// mma.sync m16n8k8 tf32: D += A*B  (acc in-place)
#define MMA_TF32(d, a, b) \
    asm volatile("mma.sync.aligned.m16n8k8.row.col.f32.tf32.tf32.f32 " \
        "{%0,%1,%2,%3}, {%4,%5,%6,%7}, {%8,%9}, {%0,%1,%2,%3};" \
        : "+f"((d)[0]), "+f"((d)[1]), "+f"((d)[2]), "+f"((d)[3]) \
        : "r"((a)[0]), "r"((a)[1]), "r"((a)[2]), "r"((a)[3]), \
          "r"((b)[0]), "r"((b)[1]))

__device__ __forceinline__ void cp_async16(uint32_t saddr, const void* gptr) {
    asm volatile("cp.async.cg.shared.global [%0], [%1], 16;"
                 :: "r"(saddr), "l"(gptr));
}
#define CP_COMMIT() asm volatile("cp.async.commit_group;" ::: "memory")
#define CP_WAIT(n)  asm volatile("cp.async.wait_group %0;" :: "n"(n) : "memory")

__device__ __forceinline__ uint32_t smem_u32(const void* p) {
    uint32_t a;
    asm("{ .reg .u64 t; cvta.to.shared.u64 t, %1; cvt.u32.u64 %0, t; }"
        : "=r"(a) : "l"(p));
    return a;
}

// ---------------------------------------------------------------------------
// Elementwise tf32 rounding pre-pass (float4-wide)
// ---------------------------------------------------------------------------
__global__ void tf32_round_kernel(const float4* __restrict__ in,
                                  float4* __restrict__ outp, int n4)
{
    int i = blockIdx.x * blockDim.x + threadIdx.x;
    if (i >= n4) return;
    float4 v = in[i];
    float4 o;
    o.x = __uint_as_float(f2tf32(v.x));
    o.y = __uint_as_float(f2tf32(v.y));
    o.z = __uint_as_float(f2tf32(v.z));
    o.w = __uint_as_float(f2tf32(v.w));
    outp[i] = o;
}

// ---------------------------------------------------------------------------
// RoPE cos/sin table: g_rope[t*64 + i] = (cos(t*theta_i), sin(t*theta_i))
// ---------------------------------------------------------------------------
__global__ void rope_table_kernel(float2* __restrict__ tab)
{
    int idx = blockIdx.x * blockDim.x + threadIdx.x;
    if (idx >= TT * 64) return;
    int tpos = idx >> 6;
    int i    = idx & 63;
    float theta = 1.0f / powf(10000.0f, (float)i / 64.0f);
    float ang   = (float)tpos * theta;
    float2 cs;
    cs.x = cosf(ang);
    cs.y = sinf(ang);
    tab[idx] = cs;
}

// ---------------------------------------------------------------------------
// TF32 tensor-core GEMM, cp.async 3-stage, CTA tile 128x128, warp tile 32x64.
// 2 CTAs/SM for cross-CTA latency hiding. Optional fused RoPE epilogue.
// out[m,n] = sum_k A[m,k]*W[n,k] + bias[n]
// ---------------------------------------------------------------------------
#define GBK 32
#define APITCH 36                        // u32 per row (32 + 4 pad)
#define TILE_U32 (128 * APITCH)
#define STAGE_U32 (2 * TILE_U32)
#define NSTAGE 3
#define GEMM_SMEM_BYTES (NSTAGE * STAGE_U32 * 4)   // 110592

__global__ void __launch_bounds__(256, 2) gemm_cp_kernel(
    const float* __restrict__ A, const float* __restrict__ W,
    const float* __restrict__ bias, float* __restrict__ out,
    const float2* __restrict__ rope, int do_rope,
    int M, int N, int K)
{
    extern __shared__ __align__(16) uint32_t gsm[];
    const uint32_t sbase = smem_u32(gsm);

    const int t = threadIdx.x, lane = t & 31, wid = t >> 5;
    const int wm = wid & 3, wn = wid >> 2;
    const int g = lane >> 2, c = lane & 3;
    const int m0 = blockIdx.y * 128, n0 = blockIdx.x * 128;

    const int lrow = t >> 3;             // 0..31
    const int lcc  = (t & 7) * 4;        // u32 col 0,4,...,28

    const float* Ab = A + (size_t)m0 * K;
    const float* Wb = W + (size_t)n0 * K;

    float acc[2][8][4];
#pragma unroll
    for (int i = 0; i < 2; i++)
#pragma unroll
        for (int j = 0; j < 8; j++)
#pragma unroll
            for (int r = 0; r < 4; r++) acc[i][j][r] = 0.f;

    const int nsteps = K >> 5;

    auto issue_stage = [&](int s, int kk) {
        const uint32_t sA = sbase + (uint32_t)(s * STAGE_U32) * 4;
        const uint32_t sB = sA + TILE_U32 * 4;
        const int kof = kk * GBK + lcc;
#pragma unroll
        for (int i = 0; i < 4; i++) {
            const int row = lrow + i * 32;
            cp_async16(sA + (row * APITCH + lcc) * 4, Ab + (size_t)row * K + kof);
            cp_async16(sB + (row * APITCH + lcc) * 4, Wb + (size_t)row * K + kof);
        }
        CP_COMMIT();
    };

    issue_stage(0, 0);
    issue_stage(1, 1);

    for (int j = 0; j < nsteps; j++) {
        const int cur = j % NSTAGE;
        CP_WAIT(1);
        __syncthreads();
        if (j + 2 < nsteps) issue_stage((j + 2) % NSTAGE, j + 2);

        const uint32_t* sA = gsm + cur * STAGE_U32;
        const uint32_t* sB = sA + TILE_U32;
#pragma unroll
        for (int ks = 0; ks < 4; ks++) {
            const int kc = ks * 8;
            uint32_t a[2][4];
#pragma unroll
            for (int mt = 0; mt < 2; mt++) {
                const int row = wm * 32 + mt * 16 + g;
                a[mt][0] = sA[row * APITCH + kc + c];
                a[mt][1] = sA[(row + 8) * APITCH + kc + c];
                a[mt][2] = sA[row * APITCH + kc + c + 4];
                a[mt][3] = sA[(row + 8) * APITCH + kc + c + 4];
            }
            uint32_t bfr[8][2];
#pragma unroll
            for (int nf = 0; nf < 8; nf++) {
                const int col = wn * 64 + nf * 8 + g;
                bfr[nf][0] = sB[col * APITCH + kc + c];
                bfr[nf][1] = sB[col * APITCH + kc + c + 4];
            }
#pragma unroll
            for (int mt = 0; mt < 2; mt++)
#pragma unroll
                for (int nf = 0; nf < 8; nf++)
                    MMA_TF32(acc[mt][nf], a[mt], bfr[nf]);
        }
        __syncthreads();
    }

    // epilogue (optionally fused RoPE on q/k sections)
#pragma unroll
    for (int mt = 0; mt < 2; mt++) {
        const int r0 = m0 + wm * 32 + mt * 16 + g;
        const int tp0 = r0 & (TT - 1);
        const int tp1 = (r0 + 8) & (TT - 1);
#pragma unroll
        for (int nf = 0; nf < 8; nf++) {
            const int col = n0 + wn * 64 + nf * 8 + c * 2;
            const float b0v = bias[col], b1v = bias[col + 1];
            float v00 = acc[mt][nf][0] + b0v;   // row r0,   col even
            float v01 = acc[mt][nf][1] + b1v;   // row r0,   col odd
            float v10 = acc[mt][nf][2] + b0v;   // row r0+8, col even
            float v11 = acc[mt][nf][3] + b1v;   // row r0+8, col odd
            if (do_rope && col < 2 * CC) {
                const int i = (col & (HDD - 1)) >> 1;
                const float2 cs0 = rope[tp0 * 64 + i];
                const float2 cs1 = rope[tp1 * 64 + i];
                float e0 = v00 * cs0.x - v01 * cs0.y;
                float o0 = v00 * cs0.y + v01 * cs0.x;
                float e1 = v10 * cs1.x - v11 * cs1.y;
                float o1 = v10 * cs1.y + v11 * cs1.x;
                v00 = e0; v01 = o0; v10 = e1; v11 = o1;
            }
            float* o0p = out + (size_t)r0 * N + col;
            float* o1p = out + (size_t)(r0 + 8) * N + col;
            o0p[0] = v00; o0p[1] = v01;
            o1p[0] = v10; o1p[1] = v11;
        }
    }
}

// ---------------------------------------------------------------------------
// Flash attention with tf32 mma.sync. One block per (b,h,qtile of 64).
// ---------------------------------------------------------------------------
#define FQP 132   // u32 pitch for Qs/Ks/Vs rows (128 + 4)
#define FSP 68    // float pitch for score tile
#define FLASH_SMEM_U32 (3 * 64 * FQP + 64 * FSP + 3 * 64)
#define FLASH_SMEM_BYTES (FLASH_SMEM_U32 * 4)

__global__ void __launch_bounds__(256) flash_mma_kernel(
    const float* __restrict__ qkv, float* __restrict__ y)
{
    extern __shared__ uint32_t fsm[];
    uint32_t* Qs = fsm;                    // [64][FQP] tf32
    uint32_t* Ks = Qs + 64 * FQP;          // [64][FQP] tf32
    uint32_t* Vs = Ks + 64 * FQP;          // [64][FQP] tf32
    float*    Ss = (float*)(Vs + 64 * FQP);// [64][FSP]
    float* mrow = Ss + 64 * FSP;
    float* lrow = mrow + 64;
    float* frow = lrow + 64;

    const int bh = blockIdx.y, b = bh >> 4, h = bh & 15;
    const int qt = blockIdx.x, q0 = qt * 64;
    const int t = threadIdx.x, lane = t & 31, wid = t >> 5;
    const int wm = wid & 3, wn = wid >> 2;
    const int g = lane >> 2, c = lane & 3;
    const float scale = 0.08838834764831845f;   // 1/sqrt(128)

    const float* Qg = qkv + ((size_t)(b * TT + q0)) * NQKV + h * HDD;
    {
        const int r = wid * 8;
#pragma unroll
        for (int i = 0; i < 8; i++) {
            float4 v = *(const float4*)(Qg + (size_t)(r + i) * NQKV + lane * 4);
            uint4 u;
            u.x = f2tf32(v.x); u.y = f2tf32(v.y); u.z = f2tf32(v.z); u.w = f2tf32(v.w);
            *(uint4*)(Qs + (r + i) * FQP + lane * 4) = u;
        }
    }
    if (t < 64) { mrow[t] = NEG_INF; lrow[t] = 0.f; }

    const int r0 = wm * 16 + g;

    float acc_o[8][4];
#pragma unroll
    for (int j = 0; j < 8; j++)
#pragma unroll
        for (int r = 0; r < 4; r++) acc_o[j][r] = 0.f;

    for (int kt = 0; kt <= qt; kt++) {
        const int k0 = kt * 64;
        const float* Kg = qkv + ((size_t)(b * TT + k0)) * NQKV + CC + h * HDD;
        const float* Vg = Kg + CC;

        __syncthreads();
        {
            const int r = wid * 8;
#pragma unroll
            for (int i = 0; i < 8; i++) {
                float4 kv = *(const float4*)(Kg + (size_t)(r + i) * NQKV + lane * 4);
                uint4 u;
                u.x = f2tf32(kv.x); u.y = f2tf32(kv.y); u.z = f2tf32(kv.z); u.w = f2tf32(kv.w);
                *(uint4*)(Ks + (r + i) * FQP + lane * 4) = u;
                float4 vv = *(const float4*)(Vg + (size_t)(r + i) * NQKV + lane * 4);
                u.x = f2tf32(vv.x); u.y = f2tf32(vv.y); u.z = f2tf32(vv.z); u.w = f2tf32(vv.w);
                *(uint4*)(Vs + (r + i) * FQP + lane * 4) = u;
            }
        }
        __syncthreads();

        float acc_s[4][4];
#pragma unroll
        for (int j = 0; j < 4; j++)
#pragma unroll
            for (int r = 0; r < 4; r++) acc_s[j][r] = 0.f;

#pragma unroll
        for (int ks = 0; ks < 16; ks++) {
            const int kc = ks * 8;
            uint32_t a[4];
            a[0] = Qs[r0 * FQP + kc + c];
            a[1] = Qs[(r0 + 8) * FQP + kc + c];
            a[2] = Qs[r0 * FQP + kc + c + 4];
            a[3] = Qs[(r0 + 8) * FQP + kc + c + 4];
#pragma unroll
            for (int nf = 0; nf < 4; nf++) {
                const int key = wn * 32 + nf * 8 + g;
                uint32_t bf[2];
                bf[0] = Ks[key * FQP + kc + c];
                bf[1] = Ks[key * FQP + kc + c + 4];
                MMA_TF32(acc_s[nf], a, bf);
            }
        }

#pragma unroll
        for (int nf = 0; nf < 4; nf++) {
            const int col = wn * 32 + nf * 8 + c * 2;
            const int kg0 = k0 + col, kg1 = k0 + col + 1;
            const int qg0 = q0 + r0, qg1 = q0 + r0 + 8;
            Ss[r0 * FSP + col]           = (kg0 <= qg0) ? acc_s[nf][0] * scale : NEG_INF;
            Ss[r0 * FSP + col + 1]       = (kg1 <= qg0) ? acc_s[nf][1] * scale : NEG_INF;
            Ss[(r0 + 8) * FSP + col]     = (kg0 <= qg1) ? acc_s[nf][2] * scale : NEG_INF;
            Ss[(r0 + 8) * FSP + col + 1] = (kg1 <= qg1) ? acc_s[nf][3] * scale : NEG_INF;
        }
        __syncthreads();

        {
            const int r = t >> 2, seg = t & 3;
            float* srow = Ss + r * FSP + seg * 16;
            float mx = NEG_INF;
#pragma unroll
            for (int j = 0; j < 16; j++) mx = fmaxf(mx, srow[j]);
            mx = fmaxf(mx, __shfl_xor_sync(0xffffffffu, mx, 1));
            mx = fmaxf(mx, __shfl_xor_sync(0xffffffffu, mx, 2));
            const float mo = mrow[r];
            const float mnew = fmaxf(mo, mx);
            float sum = 0.f;
#pragma unroll
            for (int j = 0; j < 16; j++) {
                float p = __expf(srow[j] - mnew);
                srow[j] = p;
                sum += p;
            }
            sum += __shfl_xor_sync(0xffffffffu, sum, 1);
            sum += __shfl_xor_sync(0xffffffffu, sum, 2);
            if (seg == 0) {
                const float f = __expf(mo - mnew);
                lrow[r] = lrow[r] * f + sum;
                mrow[r] = mnew;
                frow[r] = f;
            }
        }
        __syncthreads();

        {
            const float f0 = frow[r0], f1 = frow[r0 + 8];
#pragma unroll
            for (int nf = 0; nf < 8; nf++) {
                acc_o[nf][0] *= f0; acc_o[nf][1] *= f0;
                acc_o[nf][2] *= f1; acc_o[nf][3] *= f1;
            }
        }

#pragma unroll
        for (int ks = 0; ks < 8; ks++) {
            const int kk = ks * 8;
            uint32_t p[4];
            p[0] = f2tf32(Ss[r0 * FSP + kk + c]);
            p[1] = f2tf32(Ss[(r0 + 8) * FSP + kk + c]);
            p[2] = f2tf32(Ss[r0 * FSP + kk + c + 4]);
            p[3] = f2tf32(Ss[(r0 + 8) * FSP + kk + c + 4]);
#pragma unroll
            for (int nf = 0; nf < 8; nf++) {
                const int dcol = wn * 64 + nf * 8 + g;
                uint32_t vf[2];
                vf[0] = Vs[(kk + c) * FQP + dcol];
                vf[1] = Vs[(kk + c + 4) * FQP + dcol];
                MMA_TF32(acc_o[nf], p, vf);
            }
        }
    }

    // epilogue: divide by l, round to tf32 (y feeds proj GEMM as A operand)
    {
        const float li0 = 1.0f / lrow[r0];
        const float li1 = 1.0f / lrow[r0 + 8];
        float* y0 = y + ((size_t)(b * TT + q0 + r0)) * CC + h * HDD;
        float* y1 = y + ((size_t)(b * TT + q0 + r0 + 8)) * CC + h * HDD;
#pragma unroll
        for (int nf = 0; nf < 8; nf++) {
            const int col = wn * 64 + nf * 8 + c * 2;
            y0[col]     = __uint_as_float(f2tf32(acc_o[nf][0] * li0));
            y0[col + 1] = __uint_as_float(f2tf32(acc_o[nf][1] * li0));
            y1[col]     = __uint_as_float(f2tf32(acc_o[nf][2] * li1));
            y1[col + 1] = __uint_as_float(f2tf32(acc_o[nf][3] * li1));
        }
    }
}

// ---------------------------------------------------------------------------
// Launch
// ---------------------------------------------------------------------------
extern "C" void kernel_launch(void* const* d_in, const int* in_sizes, int n_in,
                              void* d_out, int out_size)
{
    const float* x      = (const float*)d_in[0];   // [2,2048,2048]
    const float* w_att  = (const float*)d_in[1];   // [6144,2048]
    const float* b_att  = (const float*)d_in[2];   // [6144]
    const float* w_proj = (const float*)d_in[3];   // [2048,2048]
    const float* b_proj = (const float*)d_in[4];   // [2048]
    float* out = (float*)d_out;                    // [2,2048,2048]

    float *qkv, *y, *xtf, *watf, *wptf;
    float2* rope;
    cudaGetSymbolAddress((void**)&qkv,  g_qkv);
    cudaGetSymbolAddress((void**)&y,    g_y);
    cudaGetSymbolAddress((void**)&xtf,  g_xtf);
    cudaGetSymbolAddress((void**)&watf, g_watf);
    cudaGetSymbolAddress((void**)&wptf, g_wptf);
    cudaGetSymbolAddress((void**)&rope, g_rope);

    cudaFuncSetAttribute(gemm_cp_kernel,
                         cudaFuncAttributeMaxDynamicSharedMemorySize,
                         GEMM_SMEM_BYTES);
    cudaFuncSetAttribute(flash_mma_kernel,
                         cudaFuncAttributeMaxDynamicSharedMemorySize,
                         FLASH_SMEM_BYTES);

    // 0) Pre-round inputs to tf32 + rope table
    {
        int n4;
        n4 = (MROWS * CC) / 4;
        tf32_round_kernel<<<(n4 + 255) / 256, 256>>>((const float4*)x, (float4*)xtf, n4);
        n4 = (NQKV * CC) / 4;
        tf32_round_kernel<<<(n4 + 255) / 256, 256>>>((const float4*)w_att, (float4*)watf, n4);
        n4 = (CC * CC) / 4;
        tf32_round_kernel<<<(n4 + 255) / 256, 256>>>((const float4*)w_proj, (float4*)wptf, n4);
        rope_table_kernel<<<(TT * 64 + 255) / 256, 256>>>(rope);
    }

    // 1) QKV projection + fused RoPE: [4096,6144] = x @ w_att^T + b_att
    gemm_cp_kernel<<<dim3(NQKV / 128, MROWS / 128), 256, GEMM_SMEM_BYTES>>>(
        xtf, watf, b_att, qkv, rope, 1, MROWS, NQKV, CC);

    // 2) Causal flash attention -> y [B,T,C] (tf32-rounded)
    flash_mma_kernel<<<dim3(TT / 64, BB * NHH), 256, FLASH_SMEM_BYTES>>>(qkv, y);

    // 3) Output projection: out = y @ w_proj^T + b_proj
    gemm_cp_kernel<<<dim3(CC / 128, MROWS / 128), 256, GEMM_SMEM_BYTES>>>(
        y, wptf, b_proj, out, rope, 0, MROWS, CC, CC);
}

// round 7
// speedup vs baseline: 3.6041x; 1.0999x over previous
#include <cuda_runtime.h>
#include <math.h>
#include <stdint.h>

// Problem constants
#define BB     2
#define TT     2048
#define CC     2048
#define NHH    16
#define HDD    128
#define NQKV   6144          // 3*C
#define MROWS  4096          // B*T

// Scratch (device globals; no allocation allowed)
__device__ float g_qkv[(size_t)MROWS * NQKV];       // 96 MB (tf32-rounded values)
__device__ float g_y[(size_t)MROWS * CC];           // 32 MB
__device__ float g_xtf[(size_t)MROWS * CC];         // 32 MB (x rounded to tf32)
__device__ float g_watf[(size_t)NQKV * CC];         // 48 MB (w_att rounded)
__device__ float g_wptf[(size_t)CC * CC];           // 16 MB (w_proj rounded)
__device__ float2 g_rope[TT * 64];                  // cos/sin table [t][i]

#define NEG_INF (__int_as_float(0xff800000))

__device__ __forceinline__ uint32_t f2tf32(float x) {
    uint32_t r;
    asm("cvt.rna.tf32.f32 %0, %1;" : "=r"(r) : "f"(x));
    return r;
}

// mma.sync m16n8k8 tf32: D += A*B  (acc in-place)
#define MMA_TF32(d, a, b) \
    asm volatile("mma.sync.aligned.m16n8k8.row.col.f32.tf32.tf32.f32 " \
        "{%0,%1,%2,%3}, {%4,%5,%6,%7}, {%8,%9}, {%0,%1,%2,%3};" \
        : "+f"((d)[0]), "+f"((d)[1]), "+f"((d)[2]), "+f"((d)[3]) \
        : "r"((a)[0]), "r"((a)[1]), "r"((a)[2]), "r"((a)[3]), \
          "r"((b)[0]), "r"((b)[1]))

__device__ __forceinline__ void cp_async16(uint32_t saddr, const void* gptr) {
    asm volatile("cp.async.cg.shared.global [%0], [%1], 16;"
                 :: "r"(saddr), "l"(gptr));
}
#define CP_COMMIT() asm volatile("cp.async.commit_group;" ::: "memory")
#define CP_WAIT(n)  asm volatile("cp.async.wait_group %0;" :: "n"(n) : "memory")

__device__ __forceinline__ uint32_t smem_u32(const void* p) {
    uint32_t a;
    asm("{ .reg .u64 t; cvta.to.shared.u64 t, %1; cvt.u32.u64 %0, t; }"
        : "=r"(a) : "l"(p));
    return a;
}

// ---------------------------------------------------------------------------
// Elementwise tf32 rounding pre-pass (float4-wide)
// ---------------------------------------------------------------------------
__global__ void tf32_round_kernel(const float4* __restrict__ in,
                                  float4* __restrict__ outp, int n4)
{
    int i = blockIdx.x * blockDim.x + threadIdx.x;
    if (i >= n4) return;
    float4 v = in[i];
    float4 o;
    o.x = __uint_as_float(f2tf32(v.x));
    o.y = __uint_as_float(f2tf32(v.y));
    o.z = __uint_as_float(f2tf32(v.z));
    o.w = __uint_as_float(f2tf32(v.w));
    outp[i] = o;
}

// ---------------------------------------------------------------------------
// RoPE cos/sin table
// ---------------------------------------------------------------------------
__global__ void rope_table_kernel(float2* __restrict__ tab)
{
    int idx = blockIdx.x * blockDim.x + threadIdx.x;
    if (idx >= TT * 64) return;
    int tpos = idx >> 6;
    int i    = idx & 63;
    float theta = 1.0f / powf(10000.0f, (float)i / 64.0f);
    float ang   = (float)tpos * theta;
    float2 cs;
    cs.x = cosf(ang);
    cs.y = sinf(ang);
    tab[idx] = cs;
}

// ---------------------------------------------------------------------------
// TF32 tensor-core GEMM, cp.async 3-stage, CTA tile 128x128, warp tile 32x64.
// 2 CTAs/SM. qkv_mode: fused RoPE on q/k sections + tf32-round ALL outputs.
// ---------------------------------------------------------------------------
#define GBK 32
#define APITCH 36
#define TILE_U32 (128 * APITCH)
#define STAGE_U32 (2 * TILE_U32)
#define NSTAGE 3
#define GEMM_SMEM_BYTES (NSTAGE * STAGE_U32 * 4)   // 110592

__global__ void __launch_bounds__(256, 2) gemm_cp_kernel(
    const float* __restrict__ A, const float* __restrict__ W,
    const float* __restrict__ bias, float* __restrict__ out,
    const float2* __restrict__ rope, int qkv_mode,
    int M, int N, int K)
{
    extern __shared__ __align__(16) uint32_t gsm[];
    const uint32_t sbase = smem_u32(gsm);

    const int t = threadIdx.x, lane = t & 31, wid = t >> 5;
    const int wm = wid & 3, wn = wid >> 2;
    const int g = lane >> 2, c = lane & 3;
    const int m0 = blockIdx.y * 128, n0 = blockIdx.x * 128;

    const int lrow = t >> 3;
    const int lcc  = (t & 7) * 4;

    const float* Ab = A + (size_t)m0 * K;
    const float* Wb = W + (size_t)n0 * K;

    float acc[2][8][4];
#pragma unroll
    for (int i = 0; i < 2; i++)
#pragma unroll
        for (int j = 0; j < 8; j++)
#pragma unroll
            for (int r = 0; r < 4; r++) acc[i][j][r] = 0.f;

    const int nsteps = K >> 5;

    auto issue_stage = [&](int s, int kk) {
        const uint32_t sA = sbase + (uint32_t)(s * STAGE_U32) * 4;
        const uint32_t sB = sA + TILE_U32 * 4;
        const int kof = kk * GBK + lcc;
#pragma unroll
        for (int i = 0; i < 4; i++) {
            const int row = lrow + i * 32;
            cp_async16(sA + (row * APITCH + lcc) * 4, Ab + (size_t)row * K + kof);
            cp_async16(sB + (row * APITCH + lcc) * 4, Wb + (size_t)row * K + kof);
        }
        CP_COMMIT();
    };

    issue_stage(0, 0);
    issue_stage(1, 1);

    for (int j = 0; j < nsteps; j++) {
        const int cur = j % NSTAGE;
        CP_WAIT(1);
        __syncthreads();
        if (j + 2 < nsteps) issue_stage((j + 2) % NSTAGE, j + 2);

        const uint32_t* sA = gsm + cur * STAGE_U32;
        const uint32_t* sB = sA + TILE_U32;
#pragma unroll
        for (int ks = 0; ks < 4; ks++) {
            const int kc = ks * 8;
            uint32_t a[2][4];
#pragma unroll
            for (int mt = 0; mt < 2; mt++) {
                const int row = wm * 32 + mt * 16 + g;
                a[mt][0] = sA[row * APITCH + kc + c];
                a[mt][1] = sA[(row + 8) * APITCH + kc + c];
                a[mt][2] = sA[row * APITCH + kc + c + 4];
                a[mt][3] = sA[(row + 8) * APITCH + kc + c + 4];
            }
            uint32_t bfr[8][2];
#pragma unroll
            for (int nf = 0; nf < 8; nf++) {
                const int col = wn * 64 + nf * 8 + g;
                bfr[nf][0] = sB[col * APITCH + kc + c];
                bfr[nf][1] = sB[col * APITCH + kc + c + 4];
            }
#pragma unroll
            for (int mt = 0; mt < 2; mt++)
#pragma unroll
                for (int nf = 0; nf < 8; nf++)
                    MMA_TF32(acc[mt][nf], a[mt], bfr[nf]);
        }
        __syncthreads();
    }

    // epilogue: qkv_mode -> RoPE on q/k sections + tf32-round everything
#pragma unroll
    for (int mt = 0; mt < 2; mt++) {
        const int r0 = m0 + wm * 32 + mt * 16 + g;
        const int tp0 = r0 & (TT - 1);
        const int tp1 = (r0 + 8) & (TT - 1);
#pragma unroll
        for (int nf = 0; nf < 8; nf++) {
            const int col = n0 + wn * 64 + nf * 8 + c * 2;
            const float b0v = bias[col], b1v = bias[col + 1];
            float v00 = acc[mt][nf][0] + b0v;
            float v01 = acc[mt][nf][1] + b1v;
            float v10 = acc[mt][nf][2] + b0v;
            float v11 = acc[mt][nf][3] + b1v;
            if (qkv_mode) {
                if (col < 2 * CC) {
                    const int i = (col & (HDD - 1)) >> 1;
                    const float2 cs0 = rope[tp0 * 64 + i];
                    const float2 cs1 = rope[tp1 * 64 + i];
                    float e0 = v00 * cs0.x - v01 * cs0.y;
                    float o0 = v00 * cs0.y + v01 * cs0.x;
                    float e1 = v10 * cs1.x - v11 * cs1.y;
                    float o1 = v10 * cs1.y + v11 * cs1.x;
                    v00 = e0; v01 = o0; v10 = e1; v11 = o1;
                }
                v00 = __uint_as_float(f2tf32(v00));
                v01 = __uint_as_float(f2tf32(v01));
                v10 = __uint_as_float(f2tf32(v10));
                v11 = __uint_as_float(f2tf32(v11));
            }
            float* o0p = out + (size_t)r0 * N + col;
            float* o1p = out + (size_t)(r0 + 8) * N + col;
            o0p[0] = v00; o0p[1] = v01;
            o1p[0] = v10; o1p[1] = v11;
        }
    }
}

// ---------------------------------------------------------------------------
// Flash attention, tf32 mma.sync, register-fragment online softmax.
// One block per (b,h,qtile of 64). Shared K/V smem buffer -> 2 CTAs/SM.
// qkv values are already tf32-rounded (GEMM epilogue).
// ---------------------------------------------------------------------------
#define FQP 132   // u32 pitch (128 + 4): conflict-free fragment reads
#define FSP 68    // pitch for P tile
#define FL_Q_U32   (64 * FQP)
#define FL_KV_U32  (64 * FQP)
#define FL_S_U32   (64 * FSP)
#define FL_STATS   (6 * 64)    // pmax[2][64], psum[2][64], mrow[64], lrow[64]
#define FLASH_SMEM_U32 (FL_Q_U32 + FL_KV_U32 + FL_S_U32 + FL_STATS)
#define FLASH_SMEM_BYTES (FLASH_SMEM_U32 * 4)      // ~86.5 KB

__global__ void __launch_bounds__(256, 2) flash_mma_kernel(
    const float* __restrict__ qkv, float* __restrict__ y)
{
    extern __shared__ uint32_t fsm[];
    uint32_t* Qs  = fsm;                      // [64][FQP]
    uint32_t* KVs = Qs + FL_Q_U32;            // [64][FQP] (K then V per tile)
    uint32_t* Ss  = KVs + FL_KV_U32;          // [64][FSP] P (tf32 bits)
    float* pmax = (float*)(Ss + FL_S_U32);    // [2][64]
    float* psum = pmax + 2 * 64;              // [2][64]
    float* mrow = psum + 2 * 64;              // [64]
    float* lrow = mrow + 64;                  // [64]

    const int bh = blockIdx.y, b = bh >> 4, h = bh & 15;
    const int qt = blockIdx.x, q0 = qt * 64;
    const int t = threadIdx.x, lane = t & 31, wid = t >> 5;
    const int wm = wid & 3, wn = wid >> 2;
    const int g = lane >> 2, c = lane & 3;
    const float scale = 0.08838834764831845f;   // 1/sqrt(128)

    // load Q tile (raw copy; already tf32 values)
    const float* Qg = qkv + ((size_t)(b * TT + q0)) * NQKV + h * HDD;
    {
        const int r = wid * 8;
#pragma unroll
        for (int i = 0; i < 8; i++)
            *(uint4*)(Qs + (r + i) * FQP + lane * 4) =
                *(const uint4*)(Qg + (size_t)(r + i) * NQKV + lane * 4);
    }
    if (t < 64) { mrow[t] = NEG_INF; lrow[t] = 0.f; }

    const int r0 = wm * 16 + g;            // rows r0, r0+8
    const int qg0 = q0 + r0, qg1 = q0 + r0 + 8;

    float acc_o[8][4];
#pragma unroll
    for (int j = 0; j < 8; j++)
#pragma unroll
        for (int r = 0; r < 4; r++) acc_o[j][r] = 0.f;

    for (int kt = 0; kt <= qt; kt++) {
        const int k0 = kt * 64;
        const float* Kg = qkv + ((size_t)(b * TT + k0)) * NQKV + CC + h * HDD;
        const float* Vg = Kg + CC;

        __syncthreads();               // Q ready (iter 0) / prev PV done
        {   // load K into KVs
            const int r = wid * 8;
#pragma unroll
            for (int i = 0; i < 8; i++)
                *(uint4*)(KVs + (r + i) * FQP + lane * 4) =
                    *(const uint4*)(Kg + (size_t)(r + i) * NQKV + lane * 4);
        }
        __syncthreads();               // K ready

        // S = Q K^T
        float acc_s[4][4];
#pragma unroll
        for (int j = 0; j < 4; j++)
#pragma unroll
            for (int r = 0; r < 4; r++) acc_s[j][r] = 0.f;
#pragma unroll
        for (int ks = 0; ks < 16; ks++) {
            const int kc = ks * 8;
            uint32_t a[4];
            a[0] = Qs[r0 * FQP + kc + c];
            a[1] = Qs[(r0 + 8) * FQP + kc + c];
            a[2] = Qs[r0 * FQP + kc + c + 4];
            a[3] = Qs[(r0 + 8) * FQP + kc + c + 4];
#pragma unroll
            for (int nf = 0; nf < 4; nf++) {
                const int key = wn * 32 + nf * 8 + g;
                uint32_t bf[2];
                bf[0] = KVs[key * FQP + kc + c];
                bf[1] = KVs[key * FQP + kc + c + 4];
                MMA_TF32(acc_s[nf], a, bf);
            }
        }

        // scale + causal mask in registers
#pragma unroll
        for (int nf = 0; nf < 4; nf++) {
            const int kg0 = k0 + wn * 32 + nf * 8 + c * 2;
            acc_s[nf][0] = (kg0     <= qg0) ? acc_s[nf][0] * scale : NEG_INF;
            acc_s[nf][1] = (kg0 + 1 <= qg0) ? acc_s[nf][1] * scale : NEG_INF;
            acc_s[nf][2] = (kg0     <= qg1) ? acc_s[nf][2] * scale : NEG_INF;
            acc_s[nf][3] = (kg0 + 1 <= qg1) ? acc_s[nf][3] * scale : NEG_INF;
        }

        // warp-level row max (over this warp's 32 keys)
        float mx0 = NEG_INF, mx1 = NEG_INF;
#pragma unroll
        for (int nf = 0; nf < 4; nf++) {
            mx0 = fmaxf(mx0, fmaxf(acc_s[nf][0], acc_s[nf][1]));
            mx1 = fmaxf(mx1, fmaxf(acc_s[nf][2], acc_s[nf][3]));
        }
        mx0 = fmaxf(mx0, __shfl_xor_sync(0xffffffffu, mx0, 1));
        mx0 = fmaxf(mx0, __shfl_xor_sync(0xffffffffu, mx0, 2));
        mx1 = fmaxf(mx1, __shfl_xor_sync(0xffffffffu, mx1, 1));
        mx1 = fmaxf(mx1, __shfl_xor_sync(0xffffffffu, mx1, 2));
        if (c == 0) {
            pmax[wn * 64 + r0]     = mx0;
            pmax[wn * 64 + r0 + 8] = mx1;
        }
        __syncthreads();               // pmax ready; all QK done -> KVs free

        // load V into KVs (overlaps with softmax arithmetic below)
        {
            const int r = wid * 8;
#pragma unroll
            for (int i = 0; i < 8; i++)
                *(uint4*)(KVs + (r + i) * FQP + lane * 4) =
                    *(const uint4*)(Vg + (size_t)(r + i) * NQKV + lane * 4);
        }

        // combine max, exp, partial sums, write P
        const float oldm0 = mrow[r0], oldm1 = mrow[r0 + 8];
        const float tmx0 = fmaxf(pmax[r0], pmax[64 + r0]);
        const float tmx1 = fmaxf(pmax[r0 + 8], pmax[64 + r0 + 8]);
        const float mnew0 = fmaxf(oldm0, tmx0);
        const float mnew1 = fmaxf(oldm1, tmx1);
        const float f0 = __expf(oldm0 - mnew0);   // 0 on first tile
        const float f1 = __expf(oldm1 - mnew1);

        float s0 = 0.f, s1 = 0.f;
#pragma unroll
        for (int nf = 0; nf < 4; nf++) {
            const int col = wn * 32 + nf * 8 + c * 2;
            float p00 = __expf(acc_s[nf][0] - mnew0);
            float p01 = __expf(acc_s[nf][1] - mnew0);
            float p10 = __expf(acc_s[nf][2] - mnew1);
            float p11 = __expf(acc_s[nf][3] - mnew1);
            s0 += p00 + p01;
            s1 += p10 + p11;
            Ss[r0 * FSP + col]           = f2tf32(p00);
            Ss[r0 * FSP + col + 1]       = f2tf32(p01);
            Ss[(r0 + 8) * FSP + col]     = f2tf32(p10);
            Ss[(r0 + 8) * FSP + col + 1] = f2tf32(p11);
        }
        s0 += __shfl_xor_sync(0xffffffffu, s0, 1);
        s0 += __shfl_xor_sync(0xffffffffu, s0, 2);
        s1 += __shfl_xor_sync(0xffffffffu, s1, 1);
        s1 += __shfl_xor_sync(0xffffffffu, s1, 2);
        if (c == 0) {
            psum[wn * 64 + r0]     = s0;
            psum[wn * 64 + r0 + 8] = s1;
        }
        __syncthreads();               // V + P + psum visible

        // stats update (owner) + O rescale
        if (wn == 0 && c == 0) {
            lrow[r0]     = lrow[r0]     * f0 + psum[r0]     + psum[64 + r0];
            lrow[r0 + 8] = lrow[r0 + 8] * f1 + psum[r0 + 8] + psum[64 + r0 + 8];
            mrow[r0]     = mnew0;
            mrow[r0 + 8] = mnew1;
        }
#pragma unroll
        for (int nf = 0; nf < 8; nf++) {
            acc_o[nf][0] *= f0; acc_o[nf][1] *= f0;
            acc_o[nf][2] *= f1; acc_o[nf][3] *= f1;
        }

        // O += P V
#pragma unroll
        for (int ks = 0; ks < 8; ks++) {
            const int kk = ks * 8;
            uint32_t p[4];
            p[0] = Ss[r0 * FSP + kk + c];
            p[1] = Ss[(r0 + 8) * FSP + kk + c];
            p[2] = Ss[r0 * FSP + kk + c + 4];
            p[3] = Ss[(r0 + 8) * FSP + kk + c + 4];
#pragma unroll
            for (int nf = 0; nf < 8; nf++) {
                const int dcol = wn * 64 + nf * 8 + g;
                uint32_t vf[2];
                vf[0] = KVs[(kk + c) * FQP + dcol];
                vf[1] = KVs[(kk + c + 4) * FQP + dcol];
                MMA_TF32(acc_o[nf], p, vf);
            }
        }
    }

    __syncthreads();   // final lrow owner-writes visible

    // epilogue: divide by l, round to tf32 (y feeds proj GEMM)
    {
        const float li0 = 1.0f / lrow[r0];
        const float li1 = 1.0f / lrow[r0 + 8];
        float* y0 = y + ((size_t)(b * TT + q0 + r0)) * CC + h * HDD;
        float* y1 = y + ((size_t)(b * TT + q0 + r0 + 8)) * CC + h * HDD;
#pragma unroll
        for (int nf = 0; nf < 8; nf++) {
            const int col = wn * 64 + nf * 8 + c * 2;
            y0[col]     = __uint_as_float(f2tf32(acc_o[nf][0] * li0));
            y0[col + 1] = __uint_as_float(f2tf32(acc_o[nf][1] * li0));
            y1[col]     = __uint_as_float(f2tf32(acc_o[nf][2] * li1));
            y1[col + 1] = __uint_as_float(f2tf32(acc_o[nf][3] * li1));
        }
    }
}

// ---------------------------------------------------------------------------
// Launch
// ---------------------------------------------------------------------------
extern "C" void kernel_launch(void* const* d_in, const int* in_sizes, int n_in,
                              void* d_out, int out_size)
{
    const float* x      = (const float*)d_in[0];   // [2,2048,2048]
    const float* w_att  = (const float*)d_in[1];   // [6144,2048]
    const float* b_att  = (const float*)d_in[2];   // [6144]
    const float* w_proj = (const float*)d_in[3];   // [2048,2048]
    const float* b_proj = (const float*)d_in[4];   // [2048]
    float* out = (float*)d_out;                    // [2,2048,2048]

    float *qkv, *y, *xtf, *watf, *wptf;
    float2* rope;
    cudaGetSymbolAddress((void**)&qkv,  g_qkv);
    cudaGetSymbolAddress((void**)&y,    g_y);
    cudaGetSymbolAddress((void**)&xtf,  g_xtf);
    cudaGetSymbolAddress((void**)&watf, g_watf);
    cudaGetSymbolAddress((void**)&wptf, g_wptf);
    cudaGetSymbolAddress((void**)&rope, g_rope);

    cudaFuncSetAttribute(gemm_cp_kernel,
                         cudaFuncAttributeMaxDynamicSharedMemorySize,
                         GEMM_SMEM_BYTES);
    cudaFuncSetAttribute(flash_mma_kernel,
                         cudaFuncAttributeMaxDynamicSharedMemorySize,
                         FLASH_SMEM_BYTES);

    // 0) Pre-round inputs to tf32 + rope table
    {
        int n4;
        n4 = (MROWS * CC) / 4;
        tf32_round_kernel<<<(n4 + 255) / 256, 256>>>((const float4*)x, (float4*)xtf, n4);
        n4 = (NQKV * CC) / 4;
        tf32_round_kernel<<<(n4 + 255) / 256, 256>>>((const float4*)w_att, (float4*)watf, n4);
        n4 = (CC * CC) / 4;
        tf32_round_kernel<<<(n4 + 255) / 256, 256>>>((const float4*)w_proj, (float4*)wptf, n4);
        rope_table_kernel<<<(TT * 64 + 255) / 256, 256>>>(rope);
    }

    // 1) QKV projection + fused RoPE + tf32 rounding of qkv
    gemm_cp_kernel<<<dim3(NQKV / 128, MROWS / 128), 256, GEMM_SMEM_BYTES>>>(
        xtf, watf, b_att, qkv, rope, 1, MROWS, NQKV, CC);

    // 2) Causal flash attention -> y [B,T,C] (tf32-rounded)
    flash_mma_kernel<<<dim3(TT / 64, BB * NHH), 256, FLASH_SMEM_BYTES>>>(qkv, y);

    // 3) Output projection: out = y @ w_proj^T + b_proj
    gemm_cp_kernel<<<dim3(CC / 128, MROWS / 128), 256, GEMM_SMEM_BYTES>>>(
        y, wptf, b_proj, out, rope, 0, MROWS, CC, CC);
}

// round 8
// speedup vs baseline: 5.7726x; 1.6017x over previous
#include <cuda_runtime.h>
#include <cuda_fp16.h>
#include <math.h>
#include <stdint.h>

// Problem constants
#define BB     2
#define TT     2048
#define CC     2048
#define NHH    16
#define HDD    128
#define NQKV   6144          // 3*C
#define MROWS  4096          // B*T

// Scratch (device globals; no allocation allowed)
__device__ __half g_qkvh[(size_t)MROWS * NQKV];     // 48 MB (q,k roped; v raw)
__device__ __half g_vt[(size_t)MROWS * CC];         // 16 MB  v transposed [b][h][d][t]
__device__ __half g_yh[(size_t)MROWS * CC];         // 16 MB
__device__ __half g_xh[(size_t)MROWS * CC];         // 16 MB
__device__ __half g_wah[(size_t)NQKV * CC];         // 24 MB
__device__ __half g_wph[(size_t)CC * CC];           // 8 MB
__device__ float2 g_rope[TT * 64];                  // cos/sin table [t][i]

#define NEG_INF (__int_as_float(0xff800000))

// mma.sync m16n8k16 fp16 -> fp32 acc (in-place)
#define MMA_F16(d, a, b) \
    asm volatile("mma.sync.aligned.m16n8k16.row.col.f32.f16.f16.f32 " \
        "{%0,%1,%2,%3}, {%4,%5,%6,%7}, {%8,%9}, {%0,%1,%2,%3};" \
        : "+f"((d)[0]), "+f"((d)[1]), "+f"((d)[2]), "+f"((d)[3]) \
        : "r"((a)[0]), "r"((a)[1]), "r"((a)[2]), "r"((a)[3]), \
          "r"((b)[0]), "r"((b)[1]))

__device__ __forceinline__ void cp_async16(uint32_t saddr, const void* gptr) {
    asm volatile("cp.async.cg.shared.global [%0], [%1], 16;"
                 :: "r"(saddr), "l"(gptr));
}
#define CP_COMMIT() asm volatile("cp.async.commit_group;" ::: "memory")
#define CP_WAIT(n)  asm volatile("cp.async.wait_group %0;" :: "n"(n) : "memory")

__device__ __forceinline__ uint32_t smem_u32(const void* p) {
    uint32_t a;
    asm("{ .reg .u64 t; cvta.to.shared.u64 t, %1; cvt.u32.u64 %0, t; }"
        : "=r"(a) : "l"(p));
    return a;
}

__device__ __forceinline__ uint32_t pack_h2(float lo, float hi) {
    __half2 h = __floats2half2_rn(lo, hi);   // .x = lo (low 16 bits)
    return *(uint32_t*)&h;
}

// ---------------------------------------------------------------------------
// fp32 -> fp16 rounding pre-pass
// ---------------------------------------------------------------------------
__global__ void f2h_kernel(const float2* __restrict__ in,
                           __half2* __restrict__ outp, int n2)
{
    int i = blockIdx.x * blockDim.x + threadIdx.x;
    if (i >= n2) return;
    float2 v = in[i];
    outp[i] = __floats2half2_rn(v.x, v.y);
}

// ---------------------------------------------------------------------------
// RoPE cos/sin table
// ---------------------------------------------------------------------------
__global__ void rope_table_kernel(float2* __restrict__ tab)
{
    int idx = blockIdx.x * blockDim.x + threadIdx.x;
    if (idx >= TT * 64) return;
    int tpos = idx >> 6;
    int i    = idx & 63;
    float theta = 1.0f / powf(10000.0f, (float)i / 64.0f);
    float ang   = (float)tpos * theta;
    float2 cs;
    cs.x = cosf(ang);
    cs.y = sinf(ang);
    tab[idx] = cs;
}

// ---------------------------------------------------------------------------
// V transpose: qkvh v-section [token][h*128+d] -> vt[(b*16+h)*128+d][t]
// ---------------------------------------------------------------------------
__global__ void vtrans_kernel(const __half* __restrict__ qkvh,
                              __half* __restrict__ vt)
{
    __shared__ __half tile[32][33];
    const int bh = blockIdx.z, b = bh >> 4, h = bh & 15;
    const int t0 = blockIdx.x * 32, d0 = blockIdx.y * 32;
    const int tx = threadIdx.x;
    for (int i = threadIdx.y; i < 32; i += 8)
        tile[i][tx] = qkvh[(size_t)(b * TT + t0 + i) * NQKV + 2 * CC + h * HDD + d0 + tx];
    __syncthreads();
    for (int i = threadIdx.y; i < 32; i += 8)
        vt[((size_t)bh * HDD + d0 + i) * TT + t0 + tx] = tile[tx][i];
}

// ---------------------------------------------------------------------------
// FP16 tensor-core GEMM, cp.async 3-stage, CTA 128x128, warp 32x64, BK=64.
// qkv_mode=1: out is half*, fused RoPE on q/k sections.
// qkv_mode=0: out is float*.
// ---------------------------------------------------------------------------
#define PITCH2 36                         // u32 per row (32 data + 4 pad)
#define TILE2_U32 (128 * PITCH2)
#define STAGE2_U32 (2 * TILE2_U32)
#define NSTAGE 3
#define GEMM_SMEM_BYTES (NSTAGE * STAGE2_U32 * 4)   // 110592

__global__ void __launch_bounds__(256, 2) gemm_h_kernel(
    const __half* __restrict__ A, const __half* __restrict__ W,
    const float* __restrict__ bias, void* __restrict__ outv,
    const float2* __restrict__ rope, int qkv_mode,
    int M, int N, int K)
{
    extern __shared__ __align__(16) uint32_t gsm[];
    const uint32_t sbase = smem_u32(gsm);

    const int t = threadIdx.x, lane = t & 31, wid = t >> 5;
    const int wm = wid & 3, wn = wid >> 2;
    const int g = lane >> 2, c = lane & 3;
    const int m0 = blockIdx.y * 128, n0 = blockIdx.x * 128;

    const int lrow = t >> 3;             // 0..31
    const int lch  = t & 7;              // 16B chunk (8 halves)

    const __half* Ab = A + (size_t)m0 * K;
    const __half* Wb = W + (size_t)n0 * K;

    float acc[2][8][4];
#pragma unroll
    for (int i = 0; i < 2; i++)
#pragma unroll
        for (int j = 0; j < 8; j++)
#pragma unroll
            for (int r = 0; r < 4; r++) acc[i][j][r] = 0.f;

    const int nsteps = K >> 6;           // BK = 64 halves

    auto issue_stage = [&](int s, int kk) {
        const uint32_t sA = sbase + (uint32_t)(s * STAGE2_U32) * 4;
        const uint32_t sB = sA + TILE2_U32 * 4;
        const int kof = kk * 64 + lch * 8;
#pragma unroll
        for (int i = 0; i < 4; i++) {
            const int row = lrow + i * 32;
            cp_async16(sA + (row * PITCH2 + lch * 4) * 4, Ab + (size_t)row * K + kof);
            cp_async16(sB + (row * PITCH2 + lch * 4) * 4, Wb + (size_t)row * K + kof);
        }
        CP_COMMIT();
    };

    issue_stage(0, 0);
    issue_stage(1, 1);

    for (int j = 0; j < nsteps; j++) {
        const int cur = j % NSTAGE;
        CP_WAIT(1);
        __syncthreads();
        if (j + 2 < nsteps) issue_stage((j + 2) % NSTAGE, j + 2);

        const uint32_t* sA = gsm + cur * STAGE2_U32;
        const uint32_t* sB = sA + TILE2_U32;
#pragma unroll
        for (int ks = 0; ks < 4; ks++) {          // 4 x k16
            const int kc = ks * 8;
            uint32_t a[2][4];
#pragma unroll
            for (int mt = 0; mt < 2; mt++) {
                const int row = wm * 32 + mt * 16 + g;
                a[mt][0] = sA[row * PITCH2 + kc + c];
                a[mt][1] = sA[(row + 8) * PITCH2 + kc + c];
                a[mt][2] = sA[row * PITCH2 + kc + c + 4];
                a[mt][3] = sA[(row + 8) * PITCH2 + kc + c + 4];
            }
            uint32_t bfr[8][2];
#pragma unroll
            for (int nf = 0; nf < 8; nf++) {
                const int col = wn * 64 + nf * 8 + g;
                bfr[nf][0] = sB[col * PITCH2 + kc + c];
                bfr[nf][1] = sB[col * PITCH2 + kc + c + 4];
            }
#pragma unroll
            for (int mt = 0; mt < 2; mt++)
#pragma unroll
                for (int nf = 0; nf < 8; nf++)
                    MMA_F16(acc[mt][nf], a[mt], bfr[nf]);
        }
        __syncthreads();
    }

    // epilogue
#pragma unroll
    for (int mt = 0; mt < 2; mt++) {
        const int r0 = m0 + wm * 32 + mt * 16 + g;
        const int tp0 = r0 & (TT - 1);
        const int tp1 = (r0 + 8) & (TT - 1);
#pragma unroll
        for (int nf = 0; nf < 8; nf++) {
            const int col = n0 + wn * 64 + nf * 8 + c * 2;
            const float b0v = bias[col], b1v = bias[col + 1];
            float v00 = acc[mt][nf][0] + b0v;
            float v01 = acc[mt][nf][1] + b1v;
            float v10 = acc[mt][nf][2] + b0v;
            float v11 = acc[mt][nf][3] + b1v;
            if (qkv_mode) {
                if (col < 2 * CC) {
                    const int i = (col & (HDD - 1)) >> 1;
                    const float2 cs0 = rope[tp0 * 64 + i];
                    const float2 cs1 = rope[tp1 * 64 + i];
                    float e0 = v00 * cs0.x - v01 * cs0.y;
                    float o0 = v00 * cs0.y + v01 * cs0.x;
                    float e1 = v10 * cs1.x - v11 * cs1.y;
                    float o1 = v10 * cs1.y + v11 * cs1.x;
                    v00 = e0; v01 = o0; v10 = e1; v11 = o1;
                }
                __half* outh = (__half*)outv;
                *(uint32_t*)(outh + (size_t)r0 * N + col)       = pack_h2(v00, v01);
                *(uint32_t*)(outh + (size_t)(r0 + 8) * N + col) = pack_h2(v10, v11);
            } else {
                float* outf = (float*)outv;
                float* o0p = outf + (size_t)r0 * N + col;
                float* o1p = outf + (size_t)(r0 + 8) * N + col;
                o0p[0] = v00; o0p[1] = v01;
                o1p[0] = v10; o1p[1] = v11;
            }
        }
    }
}

// ---------------------------------------------------------------------------
// Flash attention, fp16 mma, register-fragment online softmax.
// One block per (b,h,qtile of 64). K then Vt share one smem buffer.
// ---------------------------------------------------------------------------
#define FQP2 68    // u32 pitch for Q/K rows (64 data + 4)
#define FVP2 36    // u32 pitch for Vt/P rows (32 data + 4)
#define FL_Q_U32  (64 * FQP2)     // 4352
#define FL_KV_U32 (128 * FVP2)    // 4608 (>= 64*FQP2 = 4352)
#define FL_S_U32  (64 * FVP2)     // 2304
#define FL_STATS  (6 * 64)
#define FLASH_SMEM_U32 (FL_Q_U32 + FL_KV_U32 + FL_S_U32 + FL_STATS)
#define FLASH_SMEM_BYTES (FLASH_SMEM_U32 * 4)    // ~46.6 KB

__global__ void __launch_bounds__(256, 2) flash_h_kernel(
    const __half* __restrict__ qkvh, const __half* __restrict__ vt,
    __half* __restrict__ y)
{
    extern __shared__ uint32_t fsm[];
    uint32_t* Qs  = fsm;                      // [64][FQP2] half2
    uint32_t* KVs = Qs + FL_Q_U32;            // K [64][FQP2] then Vt [128][FVP2]
    uint32_t* Ss  = KVs + FL_KV_U32;          // P [64][FVP2] half2
    float* pmax = (float*)(Ss + FL_S_U32);    // [2][64]
    float* psum = pmax + 2 * 64;              // [2][64]
    float* mrow = psum + 2 * 64;              // [64]
    float* lrow = mrow + 64;                  // [64]

    const int bh = blockIdx.y, b = bh >> 4, h = bh & 15;
    const int qt = blockIdx.x, q0 = qt * 64;
    const int t = threadIdx.x, lane = t & 31, wid = t >> 5;
    const int wm = wid & 3, wn = wid >> 2;
    const int g = lane >> 2, c = lane & 3;
    const float scale = 0.08838834764831845f;   // 1/sqrt(128)

    // load Q tile [64 tok][128 d] half
    const __half* Qg = qkvh + ((size_t)(b * TT + q0)) * NQKV + h * HDD;
    for (int idx = t; idx < 64 * 16; idx += 256) {
        const int r = idx >> 4, ch = idx & 15;
        *(uint4*)(Qs + r * FQP2 + ch * 4) =
            *(const uint4*)(Qg + (size_t)r * NQKV + ch * 8);
    }
    if (t < 64) { mrow[t] = NEG_INF; lrow[t] = 0.f; }

    const int r0 = wm * 16 + g;
    const int qg0 = q0 + r0, qg1 = q0 + r0 + 8;

    float acc_o[8][4];
#pragma unroll
    for (int j = 0; j < 8; j++)
#pragma unroll
        for (int r = 0; r < 4; r++) acc_o[j][r] = 0.f;

    for (int kt = 0; kt <= qt; kt++) {
        const int k0 = kt * 64;
        const __half* Kg = qkvh + ((size_t)(b * TT + k0)) * NQKV + CC + h * HDD;
        const __half* Vtg = vt + (size_t)bh * HDD * TT + k0;

        __syncthreads();               // Q ready / prev PV done
        for (int idx = t; idx < 64 * 16; idx += 256) {      // K tile
            const int r = idx >> 4, ch = idx & 15;
            *(uint4*)(KVs + r * FQP2 + ch * 4) =
                *(const uint4*)(Kg + (size_t)r * NQKV + ch * 8);
        }
        __syncthreads();               // K ready

        // S = Q K^T  (8 x k16 chunks over d=128)
        float acc_s[4][4];
#pragma unroll
        for (int j = 0; j < 4; j++)
#pragma unroll
            for (int r = 0; r < 4; r++) acc_s[j][r] = 0.f;
#pragma unroll
        for (int ks = 0; ks < 8; ks++) {
            const int kc = ks * 8;
            uint32_t a[4];
            a[0] = Qs[r0 * FQP2 + kc + c];
            a[1] = Qs[(r0 + 8) * FQP2 + kc + c];
            a[2] = Qs[r0 * FQP2 + kc + c + 4];
            a[3] = Qs[(r0 + 8) * FQP2 + kc + c + 4];
#pragma unroll
            for (int nf = 0; nf < 4; nf++) {
                const int key = wn * 32 + nf * 8 + g;
                uint32_t bf[2];
                bf[0] = KVs[key * FQP2 + kc + c];
                bf[1] = KVs[key * FQP2 + kc + c + 4];
                MMA_F16(acc_s[nf], a, bf);
            }
        }

        // scale + causal mask
#pragma unroll
        for (int nf = 0; nf < 4; nf++) {
            const int kg0 = k0 + wn * 32 + nf * 8 + c * 2;
            acc_s[nf][0] = (kg0     <= qg0) ? acc_s[nf][0] * scale : NEG_INF;
            acc_s[nf][1] = (kg0 + 1 <= qg0) ? acc_s[nf][1] * scale : NEG_INF;
            acc_s[nf][2] = (kg0     <= qg1) ? acc_s[nf][2] * scale : NEG_INF;
            acc_s[nf][3] = (kg0 + 1 <= qg1) ? acc_s[nf][3] * scale : NEG_INF;
        }

        // warp-level row max
        float mx0 = NEG_INF, mx1 = NEG_INF;
#pragma unroll
        for (int nf = 0; nf < 4; nf++) {
            mx0 = fmaxf(mx0, fmaxf(acc_s[nf][0], acc_s[nf][1]));
            mx1 = fmaxf(mx1, fmaxf(acc_s[nf][2], acc_s[nf][3]));
        }
        mx0 = fmaxf(mx0, __shfl_xor_sync(0xffffffffu, mx0, 1));
        mx0 = fmaxf(mx0, __shfl_xor_sync(0xffffffffu, mx0, 2));
        mx1 = fmaxf(mx1, __shfl_xor_sync(0xffffffffu, mx1, 1));
        mx1 = fmaxf(mx1, __shfl_xor_sync(0xffffffffu, mx1, 2));
        if (c == 0) {
            pmax[wn * 64 + r0]     = mx0;
            pmax[wn * 64 + r0 + 8] = mx1;
        }
        __syncthreads();               // pmax ready; KVs free

        // load Vt tile [128 d][64 tok] (overlaps softmax math)
        for (int idx = t; idx < 128 * 8; idx += 256) {
            const int r = idx >> 3, ch = idx & 7;
            *(uint4*)(KVs + r * FVP2 + ch * 4) =
                *(const uint4*)(Vtg + (size_t)r * TT + ch * 8);
        }

        // combine max, exp, partial sums, write P (fp16)
        const float oldm0 = mrow[r0], oldm1 = mrow[r0 + 8];
        const float mnew0 = fmaxf(oldm0, fmaxf(pmax[r0], pmax[64 + r0]));
        const float mnew1 = fmaxf(oldm1, fmaxf(pmax[r0 + 8], pmax[64 + r0 + 8]));
        const float f0 = __expf(oldm0 - mnew0);
        const float f1 = __expf(oldm1 - mnew1);

        float s0 = 0.f, s1 = 0.f;
#pragma unroll
        for (int nf = 0; nf < 4; nf++) {
            const int cu = wn * 16 + nf * 4 + c;   // u32 (half2) column index
            float p00 = __expf(acc_s[nf][0] - mnew0);
            float p01 = __expf(acc_s[nf][1] - mnew0);
            float p10 = __expf(acc_s[nf][2] - mnew1);
            float p11 = __expf(acc_s[nf][3] - mnew1);
            s0 += p00 + p01;
            s1 += p10 + p11;
            Ss[r0 * FVP2 + cu]       = pack_h2(p00, p01);
            Ss[(r0 + 8) * FVP2 + cu] = pack_h2(p10, p11);
        }
        s0 += __shfl_xor_sync(0xffffffffu, s0, 1);
        s0 += __shfl_xor_sync(0xffffffffu, s0, 2);
        s1 += __shfl_xor_sync(0xffffffffu, s1, 1);
        s1 += __shfl_xor_sync(0xffffffffu, s1, 2);
        if (c == 0) {
            psum[wn * 64 + r0]     = s0;
            psum[wn * 64 + r0 + 8] = s1;
        }
        __syncthreads();               // Vt + P + psum visible

        if (wn == 0 && c == 0) {
            lrow[r0]     = lrow[r0]     * f0 + psum[r0]     + psum[64 + r0];
            lrow[r0 + 8] = lrow[r0 + 8] * f1 + psum[r0 + 8] + psum[64 + r0 + 8];
            mrow[r0]     = mnew0;
            mrow[r0 + 8] = mnew1;
        }
#pragma unroll
        for (int nf = 0; nf < 8; nf++) {
            acc_o[nf][0] *= f0; acc_o[nf][1] *= f0;
            acc_o[nf][2] *= f1; acc_o[nf][3] *= f1;
        }

        // O += P V   (4 x k16 chunks over keys=64)
#pragma unroll
        for (int ks = 0; ks < 4; ks++) {
            const int kc = ks * 8;
            uint32_t p[4];
            p[0] = Ss[r0 * FVP2 + kc + c];
            p[1] = Ss[(r0 + 8) * FVP2 + kc + c];
            p[2] = Ss[r0 * FVP2 + kc + c + 4];
            p[3] = Ss[(r0 + 8) * FVP2 + kc + c + 4];
#pragma unroll
            for (int nf = 0; nf < 8; nf++) {
                const int dcol = wn * 64 + nf * 8 + g;
                uint32_t vf[2];
                vf[0] = KVs[dcol * FVP2 + kc + c];
                vf[1] = KVs[dcol * FVP2 + kc + c + 4];
                MMA_F16(acc_o[nf], p, vf);
            }
        }
    }

    __syncthreads();

    // epilogue: divide by l, store fp16 y
    {
        const float li0 = 1.0f / lrow[r0];
        const float li1 = 1.0f / lrow[r0 + 8];
        __half* y0 = y + ((size_t)(b * TT + q0 + r0)) * CC + h * HDD;
        __half* y1 = y + ((size_t)(b * TT + q0 + r0 + 8)) * CC + h * HDD;
#pragma unroll
        for (int nf = 0; nf < 8; nf++) {
            const int col = wn * 64 + nf * 8 + c * 2;
            *(uint32_t*)(y0 + col) = pack_h2(acc_o[nf][0] * li0, acc_o[nf][1] * li0);
            *(uint32_t*)(y1 + col) = pack_h2(acc_o[nf][2] * li1, acc_o[nf][3] * li1);
        }
    }
}

// ---------------------------------------------------------------------------
// Launch
// ---------------------------------------------------------------------------
extern "C" void kernel_launch(void* const* d_in, const int* in_sizes, int n_in,
                              void* d_out, int out_size)
{
    const float* x      = (const float*)d_in[0];   // [2,2048,2048]
    const float* w_att  = (const float*)d_in[1];   // [6144,2048]
    const float* b_att  = (const float*)d_in[2];   // [6144]
    const float* w_proj = (const float*)d_in[3];   // [2048,2048]
    const float* b_proj = (const float*)d_in[4];   // [2048]
    float* out = (float*)d_out;                    // [2,2048,2048]

    __half *qkvh, *vth, *yh, *xh, *wah, *wph;
    float2* rope;
    cudaGetSymbolAddress((void**)&qkvh, g_qkvh);
    cudaGetSymbolAddress((void**)&vth,  g_vt);
    cudaGetSymbolAddress((void**)&yh,   g_yh);
    cudaGetSymbolAddress((void**)&xh,   g_xh);
    cudaGetSymbolAddress((void**)&wah,  g_wah);
    cudaGetSymbolAddress((void**)&wph,  g_wph);
    cudaGetSymbolAddress((void**)&rope, g_rope);

    cudaFuncSetAttribute(gemm_h_kernel,
                         cudaFuncAttributeMaxDynamicSharedMemorySize,
                         GEMM_SMEM_BYTES);
    cudaFuncSetAttribute(flash_h_kernel,
                         cudaFuncAttributeMaxDynamicSharedMemorySize,
                         FLASH_SMEM_BYTES);

    // 0) Pre-round inputs to fp16 + rope table
    {
        int n2;
        n2 = (MROWS * CC) / 2;
        f2h_kernel<<<(n2 + 255) / 256, 256>>>((const float2*)x, (__half2*)xh, n2);
        n2 = (NQKV * CC) / 2;
        f2h_kernel<<<(n2 + 255) / 256, 256>>>((const float2*)w_att, (__half2*)wah, n2);
        n2 = (CC * CC) / 2;
        f2h_kernel<<<(n2 + 255) / 256, 256>>>((const float2*)w_proj, (__half2*)wph, n2);
        rope_table_kernel<<<(TT * 64 + 255) / 256, 256>>>(rope);
    }

    // 1) QKV projection + fused RoPE -> fp16 qkv
    gemm_h_kernel<<<dim3(NQKV / 128, MROWS / 128), 256, GEMM_SMEM_BYTES>>>(
        xh, wah, b_att, qkvh, rope, 1, MROWS, NQKV, CC);

    // 2) Transpose V section -> [b][h][d][t]
    vtrans_kernel<<<dim3(TT / 32, HDD / 32, BB * NHH), dim3(32, 8)>>>(qkvh, vth);

    // 3) Causal flash attention -> yh [B,T,C] fp16
    flash_h_kernel<<<dim3(TT / 64, BB * NHH), 256, FLASH_SMEM_BYTES>>>(qkvh, vth, yh);

    // 4) Output projection: out = y @ w_proj^T + b_proj (fp32 out)
    gemm_h_kernel<<<dim3(CC / 128, MROWS / 128), 256, GEMM_SMEM_BYTES>>>(
        yh, wph, b_proj, out, rope, 0, MROWS, CC, CC);
}

// round 9
// speedup vs baseline: 7.5274x; 1.3040x over previous
#include <cuda_runtime.h>
#include <cuda_fp16.h>
#include <math.h>
#include <stdint.h>

// Problem constants
#define BB     2
#define TT     2048
#define CC     2048
#define NHH    16
#define HDD    128
#define NQKV   6144          // 3*C
#define MROWS  4096          // B*T

// Scratch (device globals; no allocation allowed)
__device__ __half g_qkvh[(size_t)MROWS * NQKV];     // 48 MB (q,k roped; v raw)
__device__ __half g_vt[(size_t)MROWS * CC];         // 16 MB  v transposed [b][h][d][t]
__device__ __half g_yh[(size_t)MROWS * CC];         // 16 MB
__device__ __half g_xh[(size_t)MROWS * CC];         // 16 MB
__device__ __half g_wah[(size_t)NQKV * CC];         // 24 MB
__device__ __half g_wph[(size_t)CC * CC];           // 8 MB
__device__ float2 g_rope[TT * 64];                  // cos/sin table [t][i]

#define NEG_INF (__int_as_float(0xff800000))

// mma.sync m16n8k16 fp16 -> fp32 acc (in-place)
#define MMA_F16(d, a, b) \
    asm volatile("mma.sync.aligned.m16n8k16.row.col.f32.f16.f16.f32 " \
        "{%0,%1,%2,%3}, {%4,%5,%6,%7}, {%8,%9}, {%0,%1,%2,%3};" \
        : "+f"((d)[0]), "+f"((d)[1]), "+f"((d)[2]), "+f"((d)[3]) \
        : "r"((a)[0]), "r"((a)[1]), "r"((a)[2]), "r"((a)[3]), \
          "r"((b)[0]), "r"((b)[1]))

// ldmatrix x4 (non-transposed)
#define LDSM_X4(r0, r1, r2, r3, addr) \
    asm volatile("ldmatrix.sync.aligned.m8n8.x4.shared.b16 {%0,%1,%2,%3}, [%4];" \
        : "=r"(r0), "=r"(r1), "=r"(r2), "=r"(r3) : "r"(addr))

__device__ __forceinline__ void cp_async16(uint32_t saddr, const void* gptr) {
    asm volatile("cp.async.cg.shared.global [%0], [%1], 16;"
                 :: "r"(saddr), "l"(gptr));
}
#define CP_COMMIT() asm volatile("cp.async.commit_group;" ::: "memory")
#define CP_WAIT(n)  asm volatile("cp.async.wait_group %0;" :: "n"(n) : "memory")

__device__ __forceinline__ uint32_t smem_u32(const void* p) {
    uint32_t a;
    asm("{ .reg .u64 t; cvta.to.shared.u64 t, %1; cvt.u32.u64 %0, t; }"
        : "=r"(a) : "l"(p));
    return a;
}

__device__ __forceinline__ uint32_t pack_h2(float lo, float hi) {
    __half2 h = __floats2half2_rn(lo, hi);
    return *(uint32_t*)&h;
}

// ---------------------------------------------------------------------------
// fp32 -> fp16 rounding pre-pass
// ---------------------------------------------------------------------------
__global__ void f2h_kernel(const float2* __restrict__ in,
                           __half2* __restrict__ outp, int n2)
{
    int i = blockIdx.x * blockDim.x + threadIdx.x;
    if (i >= n2) return;
    float2 v = in[i];
    outp[i] = __floats2half2_rn(v.x, v.y);
}

// ---------------------------------------------------------------------------
// RoPE cos/sin table
// ---------------------------------------------------------------------------
__global__ void rope_table_kernel(float2* __restrict__ tab)
{
    int idx = blockIdx.x * blockDim.x + threadIdx.x;
    if (idx >= TT * 64) return;
    int tpos = idx >> 6;
    int i    = idx & 63;
    float theta = 1.0f / powf(10000.0f, (float)i / 64.0f);
    float ang   = (float)tpos * theta;
    float2 cs;
    cs.x = cosf(ang);
    cs.y = sinf(ang);
    tab[idx] = cs;
}

// ---------------------------------------------------------------------------
// V transpose: qkvh v-section [token][h*128+d] -> vt[(b*16+h)*128+d][t]
// ---------------------------------------------------------------------------
__global__ void vtrans_kernel(const __half* __restrict__ qkvh,
                              __half* __restrict__ vt)
{
    __shared__ __half tile[32][33];
    const int bh = blockIdx.z, b = bh >> 4, h = bh & 15;
    const int t0 = blockIdx.x * 32, d0 = blockIdx.y * 32;
    const int tx = threadIdx.x;
    for (int i = threadIdx.y; i < 32; i += 8)
        tile[i][tx] = qkvh[(size_t)(b * TT + t0 + i) * NQKV + 2 * CC + h * HDD + d0 + tx];
    __syncthreads();
    for (int i = threadIdx.y; i < 32; i += 8)
        vt[((size_t)bh * HDD + d0 + i) * TT + t0 + tx] = tile[tx][i];
}

// ---------------------------------------------------------------------------
// FP16 tensor-core GEMM, cp.async 3-stage, CTA 128x128, warp 32x64, BK=64.
// Fragment loads via ldmatrix.x4.
// ---------------------------------------------------------------------------
#define PITCH2 36                         // u32 per row (32 data + 4 pad)
#define TILE2_U32 (128 * PITCH2)
#define STAGE2_U32 (2 * TILE2_U32)
#define NSTAGE 3
#define GEMM_SMEM_BYTES (NSTAGE * STAGE2_U32 * 4)   // 110592

__global__ void __launch_bounds__(256, 2) gemm_h_kernel(
    const __half* __restrict__ A, const __half* __restrict__ W,
    const float* __restrict__ bias, void* __restrict__ outv,
    const float2* __restrict__ rope, int qkv_mode,
    int M, int N, int K)
{
    extern __shared__ __align__(16) uint32_t gsm[];
    const uint32_t sbase = smem_u32(gsm);

    const int t = threadIdx.x, lane = t & 31, wid = t >> 5;
    const int wm = wid & 3, wn = wid >> 2;
    const int g = lane >> 2, c = lane & 3;
    const int m0 = blockIdx.y * 128, n0 = blockIdx.x * 128;

    // ldmatrix per-lane mappings
    const int quad   = lane >> 3;
    const int lrow_a = (lane & 7) + ((quad & 1) << 3);   // A: (m0,k0)(m8,k0)(m0,k8)(m8,k8)
    const int kseg_a = (quad >> 1) << 2;                 // u32 offset 0 or 4
    const int lrow_b = (lane & 7) + ((quad >> 1) << 3);  // B: (n0,k0)(n0,k8)(n8,k0)(n8,k8)
    const int kseg_b = (quad & 1) << 2;

    const int lrow = t >> 3;             // loader row 0..31
    const int lch  = t & 7;              // loader 16B chunk

    const __half* Ab = A + (size_t)m0 * K;
    const __half* Wb = W + (size_t)n0 * K;

    float acc[2][8][4];
#pragma unroll
    for (int i = 0; i < 2; i++)
#pragma unroll
        for (int j = 0; j < 8; j++)
#pragma unroll
            for (int r = 0; r < 4; r++) acc[i][j][r] = 0.f;

    const int nsteps = K >> 6;           // BK = 64 halves

    auto issue_stage = [&](int s, int kk) {
        const uint32_t sA = sbase + (uint32_t)(s * STAGE2_U32) * 4;
        const uint32_t sB = sA + TILE2_U32 * 4;
        const int kof = kk * 64 + lch * 8;
#pragma unroll
        for (int i = 0; i < 4; i++) {
            const int row = lrow + i * 32;
            cp_async16(sA + (row * PITCH2 + lch * 4) * 4, Ab + (size_t)row * K + kof);
            cp_async16(sB + (row * PITCH2 + lch * 4) * 4, Wb + (size_t)row * K + kof);
        }
        CP_COMMIT();
    };

    issue_stage(0, 0);
    issue_stage(1, 1);

    for (int j = 0; j < nsteps; j++) {
        const int cur = j % NSTAGE;
        CP_WAIT(1);
        __syncthreads();
        if (j + 2 < nsteps) issue_stage((j + 2) % NSTAGE, j + 2);

        const uint32_t sAb = sbase + (uint32_t)(cur * STAGE2_U32) * 4;
        const uint32_t sBb = sAb + TILE2_U32 * 4;
#pragma unroll
        for (int ks = 0; ks < 4; ks++) {          // 4 x k16
            const int kc = ks * 8;
            uint32_t a[2][4];
#pragma unroll
            for (int mt = 0; mt < 2; mt++) {
                const uint32_t ad = sAb +
                    (uint32_t)(((wm * 32 + mt * 16 + lrow_a) * PITCH2) + kc + kseg_a) * 4;
                LDSM_X4(a[mt][0], a[mt][1], a[mt][2], a[mt][3], ad);
            }
            uint32_t bfr[8][2];
#pragma unroll
            for (int p = 0; p < 4; p++) {
                const uint32_t bd = sBb +
                    (uint32_t)(((wn * 64 + p * 16 + lrow_b) * PITCH2) + kc + kseg_b) * 4;
                LDSM_X4(bfr[2 * p][0], bfr[2 * p][1],
                        bfr[2 * p + 1][0], bfr[2 * p + 1][1], bd);
            }
#pragma unroll
            for (int mt = 0; mt < 2; mt++)
#pragma unroll
                for (int nf = 0; nf < 8; nf++)
                    MMA_F16(acc[mt][nf], a[mt], bfr[nf]);
        }
        __syncthreads();
    }

    // epilogue
#pragma unroll
    for (int mt = 0; mt < 2; mt++) {
        const int r0 = m0 + wm * 32 + mt * 16 + g;
        const int tp0 = r0 & (TT - 1);
        const int tp1 = (r0 + 8) & (TT - 1);
#pragma unroll
        for (int nf = 0; nf < 8; nf++) {
            const int col = n0 + wn * 64 + nf * 8 + c * 2;
            const float b0v = bias[col], b1v = bias[col + 1];
            float v00 = acc[mt][nf][0] + b0v;
            float v01 = acc[mt][nf][1] + b1v;
            float v10 = acc[mt][nf][2] + b0v;
            float v11 = acc[mt][nf][3] + b1v;
            if (qkv_mode) {
                if (col < 2 * CC) {
                    const int i = (col & (HDD - 1)) >> 1;
                    const float2 cs0 = rope[tp0 * 64 + i];
                    const float2 cs1 = rope[tp1 * 64 + i];
                    float e0 = v00 * cs0.x - v01 * cs0.y;
                    float o0 = v00 * cs0.y + v01 * cs0.x;
                    float e1 = v10 * cs1.x - v11 * cs1.y;
                    float o1 = v10 * cs1.y + v11 * cs1.x;
                    v00 = e0; v01 = o0; v10 = e1; v11 = o1;
                }
                __half* outh = (__half*)outv;
                *(uint32_t*)(outh + (size_t)r0 * N + col)       = pack_h2(v00, v01);
                *(uint32_t*)(outh + (size_t)(r0 + 8) * N + col) = pack_h2(v10, v11);
            } else {
                float* outf = (float*)outv;
                float* o0p = outf + (size_t)r0 * N + col;
                float* o1p = outf + (size_t)(r0 + 8) * N + col;
                o0p[0] = v00; o0p[1] = v01;
                o1p[0] = v10; o1p[1] = v11;
            }
        }
    }
}

// ---------------------------------------------------------------------------
// Flash attention, fp16 mma, ldmatrix fragments, cp.async tile loads.
// One block per (b,h,qtile of 64). K then Vt share one smem buffer.
// ---------------------------------------------------------------------------
#define FQP2 68    // u32 pitch for Q/K rows (64 data + 4)
#define FVP2 36    // u32 pitch for Vt/P rows (32 data + 4)
#define FL_Q_U32  (64 * FQP2)     // 4352
#define FL_KV_U32 (128 * FVP2)    // 4608 (>= 64*FQP2 = 4352)
#define FL_S_U32  (64 * FVP2)     // 2304
#define FL_STATS  (6 * 64)
#define FLASH_SMEM_U32 (FL_Q_U32 + FL_KV_U32 + FL_S_U32 + FL_STATS)
#define FLASH_SMEM_BYTES (FLASH_SMEM_U32 * 4)    // ~46.6 KB

__global__ void __launch_bounds__(256, 2) flash_h_kernel(
    const __half* __restrict__ qkvh, const __half* __restrict__ vt,
    __half* __restrict__ y)
{
    extern __shared__ uint32_t fsm[];
    uint32_t* Ss  = fsm + FL_Q_U32 + FL_KV_U32;
    float* pmax = (float*)(Ss + FL_S_U32);
    float* psum = pmax + 2 * 64;
    float* mrow = psum + 2 * 64;
    float* lrow = mrow + 64;

    const uint32_t Qsb  = smem_u32(fsm);
    const uint32_t KVsb = Qsb + FL_Q_U32 * 4;
    const uint32_t Ssb  = KVsb + FL_KV_U32 * 4;

    const int bh = blockIdx.y, b = bh >> 4, h = bh & 15;
    const int qt = blockIdx.x, q0 = qt * 64;
    const int t = threadIdx.x, lane = t & 31, wid = t >> 5;
    const int wm = wid & 3, wn = wid >> 2;
    const int g = lane >> 2, c = lane & 3;
    const float scale = 0.08838834764831845f;   // 1/sqrt(128)

    const int quad   = lane >> 3;
    const int lrow_a = (lane & 7) + ((quad & 1) << 3);
    const int kseg_a = (quad >> 1) << 2;
    const int lrow_b = (lane & 7) + ((quad >> 1) << 3);
    const int kseg_b = (quad & 1) << 2;

    // load Q tile [64 tok][128 d] via cp.async
    const __half* Qg = qkvh + ((size_t)(b * TT + q0)) * NQKV + h * HDD;
    {
        const int r = t >> 2, ch = t & 3;       // 64 rows x 4 chunks... (16 chunks/row)
#pragma unroll
        for (int i = 0; i < 4; i++) {
            const int idx = t + i * 256;
            const int rr = idx >> 4, cc = idx & 15;
            cp_async16(Qsb + (rr * FQP2 + cc * 4) * 4,
                       Qg + (size_t)rr * NQKV + cc * 8);
        }
        (void)r; (void)ch;
        CP_COMMIT();
    }
    if (t < 64) { mrow[t] = NEG_INF; lrow[t] = 0.f; }

    const int r0 = wm * 16 + g;
    const int qg0 = q0 + r0, qg1 = q0 + r0 + 8;

    float acc_o[8][4];
#pragma unroll
    for (int j = 0; j < 8; j++)
#pragma unroll
        for (int r = 0; r < 4; r++) acc_o[j][r] = 0.f;

    for (int kt = 0; kt <= qt; kt++) {
        const int k0 = kt * 64;
        const __half* Kg = qkvh + ((size_t)(b * TT + k0)) * NQKV + CC + h * HDD;
        const __half* Vtg = vt + (size_t)bh * HDD * TT + k0;

        __syncthreads();               // prev iter done with KVs/Ss
#pragma unroll
        for (int i = 0; i < 4; i++) {  // K tile (64 rows x 16 chunks)
            const int idx = t + i * 256;
            const int rr = idx >> 4, cc = idx & 15;
            cp_async16(KVsb + (rr * FQP2 + cc * 4) * 4,
                       Kg + (size_t)rr * NQKV + cc * 8);
        }
        CP_COMMIT();
        CP_WAIT(0);
        __syncthreads();               // Q + K ready

        // S = Q K^T  (8 x k16 chunks over d=128)
        float acc_s[4][4];
#pragma unroll
        for (int j = 0; j < 4; j++)
#pragma unroll
            for (int r = 0; r < 4; r++) acc_s[j][r] = 0.f;
#pragma unroll
        for (int ks = 0; ks < 8; ks++) {
            const int kc = ks * 8;
            uint32_t a[4];
            {
                const uint32_t ad = Qsb +
                    (uint32_t)(((wm * 16 + lrow_a) * FQP2) + kc + kseg_a) * 4;
                LDSM_X4(a[0], a[1], a[2], a[3], ad);
            }
            uint32_t bf[4][2];
#pragma unroll
            for (int p = 0; p < 2; p++) {
                const uint32_t bd = KVsb +
                    (uint32_t)(((wn * 32 + p * 16 + lrow_b) * FQP2) + kc + kseg_b) * 4;
                LDSM_X4(bf[2 * p][0], bf[2 * p][1],
                        bf[2 * p + 1][0], bf[2 * p + 1][1], bd);
            }
#pragma unroll
            for (int nf = 0; nf < 4; nf++)
                MMA_F16(acc_s[nf], a, bf[nf]);
        }

        // scale + causal mask
#pragma unroll
        for (int nf = 0; nf < 4; nf++) {
            const int kg0 = k0 + wn * 32 + nf * 8 + c * 2;
            acc_s[nf][0] = (kg0     <= qg0) ? acc_s[nf][0] * scale : NEG_INF;
            acc_s[nf][1] = (kg0 + 1 <= qg0) ? acc_s[nf][1] * scale : NEG_INF;
            acc_s[nf][2] = (kg0     <= qg1) ? acc_s[nf][2] * scale : NEG_INF;
            acc_s[nf][3] = (kg0 + 1 <= qg1) ? acc_s[nf][3] * scale : NEG_INF;
        }

        // warp-level row max
        float mx0 = NEG_INF, mx1 = NEG_INF;
#pragma unroll
        for (int nf = 0; nf < 4; nf++) {
            mx0 = fmaxf(mx0, fmaxf(acc_s[nf][0], acc_s[nf][1]));
            mx1 = fmaxf(mx1, fmaxf(acc_s[nf][2], acc_s[nf][3]));
        }
        mx0 = fmaxf(mx0, __shfl_xor_sync(0xffffffffu, mx0, 1));
        mx0 = fmaxf(mx0, __shfl_xor_sync(0xffffffffu, mx0, 2));
        mx1 = fmaxf(mx1, __shfl_xor_sync(0xffffffffu, mx1, 1));
        mx1 = fmaxf(mx1, __shfl_xor_sync(0xffffffffu, mx1, 2));
        if (c == 0) {
            pmax[wn * 64 + r0]     = mx0;
            pmax[wn * 64 + r0 + 8] = mx1;
        }
        __syncthreads();               // pmax ready; KVs free

        // load Vt tile [128 d][64 tok] via cp.async (overlaps softmax math)
#pragma unroll
        for (int i = 0; i < 4; i++) {
            const int idx = t + i * 256;
            const int rr = idx >> 3, cc = idx & 7;
            cp_async16(KVsb + (rr * FVP2 + cc * 4) * 4,
                       Vtg + (size_t)rr * TT + cc * 8);
        }
        CP_COMMIT();

        // combine max, exp, partial sums, write P (fp16)
        const float oldm0 = mrow[r0], oldm1 = mrow[r0 + 8];
        const float mnew0 = fmaxf(oldm0, fmaxf(pmax[r0], pmax[64 + r0]));
        const float mnew1 = fmaxf(oldm1, fmaxf(pmax[r0 + 8], pmax[64 + r0 + 8]));
        const float f0 = __expf(oldm0 - mnew0);
        const float f1 = __expf(oldm1 - mnew1);

        float s0 = 0.f, s1 = 0.f;
        uint32_t* Ssu = (uint32_t*)fsm + FL_Q_U32 + FL_KV_U32;
#pragma unroll
        for (int nf = 0; nf < 4; nf++) {
            const int cu = wn * 16 + nf * 4 + c;
            float p00 = __expf(acc_s[nf][0] - mnew0);
            float p01 = __expf(acc_s[nf][1] - mnew0);
            float p10 = __expf(acc_s[nf][2] - mnew1);
            float p11 = __expf(acc_s[nf][3] - mnew1);
            s0 += p00 + p01;
            s1 += p10 + p11;
            Ssu[r0 * FVP2 + cu]       = pack_h2(p00, p01);
            Ssu[(r0 + 8) * FVP2 + cu] = pack_h2(p10, p11);
        }
        s0 += __shfl_xor_sync(0xffffffffu, s0, 1);
        s0 += __shfl_xor_sync(0xffffffffu, s0, 2);
        s1 += __shfl_xor_sync(0xffffffffu, s1, 1);
        s1 += __shfl_xor_sync(0xffffffffu, s1, 2);
        if (c == 0) {
            psum[wn * 64 + r0]     = s0;
            psum[wn * 64 + r0 + 8] = s1;
        }
        CP_WAIT(0);
        __syncthreads();               // Vt + P + psum visible

        if (wn == 0 && c == 0) {
            lrow[r0]     = lrow[r0]     * f0 + psum[r0]     + psum[64 + r0];
            lrow[r0 + 8] = lrow[r0 + 8] * f1 + psum[r0 + 8] + psum[64 + r0 + 8];
            mrow[r0]     = mnew0;
            mrow[r0 + 8] = mnew1;
        }
#pragma unroll
        for (int nf = 0; nf < 8; nf++) {
            acc_o[nf][0] *= f0; acc_o[nf][1] *= f0;
            acc_o[nf][2] *= f1; acc_o[nf][3] *= f1;
        }

        // O += P V   (4 x k16 chunks over keys=64)
#pragma unroll
        for (int ks = 0; ks < 4; ks++) {
            const int kc = ks * 8;
            uint32_t p[4];
            {
                const uint32_t pd = Ssb +
                    (uint32_t)(((wm * 16 + lrow_a) * FVP2) + kc + kseg_a) * 4;
                LDSM_X4(p[0], p[1], p[2], p[3], pd);
            }
            uint32_t vf[8][2];
#pragma unroll
            for (int pp = 0; pp < 4; pp++) {
                const uint32_t vd = KVsb +
                    (uint32_t)(((wn * 64 + pp * 16 + lrow_b) * FVP2) + kc + kseg_b) * 4;
                LDSM_X4(vf[2 * pp][0], vf[2 * pp][1],
                        vf[2 * pp + 1][0], vf[2 * pp + 1][1], vd);
            }
#pragma unroll
            for (int nf = 0; nf < 8; nf++)
                MMA_F16(acc_o[nf], p, vf[nf]);
        }
    }

    __syncthreads();

    // epilogue: divide by l, store fp16 y
    {
        const float li0 = 1.0f / lrow[r0];
        const float li1 = 1.0f / lrow[r0 + 8];
        __half* y0 = y + ((size_t)(b * TT + q0 + r0)) * CC + h * HDD;
        __half* y1 = y + ((size_t)(b * TT + q0 + r0 + 8)) * CC + h * HDD;
#pragma unroll
        for (int nf = 0; nf < 8; nf++) {
            const int col = wn * 64 + nf * 8 + c * 2;
            *(uint32_t*)(y0 + col) = pack_h2(acc_o[nf][0] * li0, acc_o[nf][1] * li0);
            *(uint32_t*)(y1 + col) = pack_h2(acc_o[nf][2] * li1, acc_o[nf][3] * li1);
        }
    }
}

// ---------------------------------------------------------------------------
// Launch
// ---------------------------------------------------------------------------
extern "C" void kernel_launch(void* const* d_in, const int* in_sizes, int n_in,
                              void* d_out, int out_size)
{
    const float* x      = (const float*)d_in[0];   // [2,2048,2048]
    const float* w_att  = (const float*)d_in[1];   // [6144,2048]
    const float* b_att  = (const float*)d_in[2];   // [6144]
    const float* w_proj = (const float*)d_in[3];   // [2048,2048]
    const float* b_proj = (const float*)d_in[4];   // [2048]
    float* out = (float*)d_out;                    // [2,2048,2048]

    __half *qkvh, *vth, *yh, *xh, *wah, *wph;
    float2* rope;
    cudaGetSymbolAddress((void**)&qkvh, g_qkvh);
    cudaGetSymbolAddress((void**)&vth,  g_vt);
    cudaGetSymbolAddress((void**)&yh,   g_yh);
    cudaGetSymbolAddress((void**)&xh,   g_xh);
    cudaGetSymbolAddress((void**)&wah,  g_wah);
    cudaGetSymbolAddress((void**)&wph,  g_wph);
    cudaGetSymbolAddress((void**)&rope, g_rope);

    cudaFuncSetAttribute(gemm_h_kernel,
                         cudaFuncAttributeMaxDynamicSharedMemorySize,
                         GEMM_SMEM_BYTES);
    cudaFuncSetAttribute(flash_h_kernel,
                         cudaFuncAttributeMaxDynamicSharedMemorySize,
                         FLASH_SMEM_BYTES);

    // 0) Pre-round inputs to fp16 + rope table
    {
        int n2;
        n2 = (MROWS * CC) / 2;
        f2h_kernel<<<(n2 + 255) / 256, 256>>>((const float2*)x, (__half2*)xh, n2);
        n2 = (NQKV * CC) / 2;
        f2h_kernel<<<(n2 + 255) / 256, 256>>>((const float2*)w_att, (__half2*)wah, n2);
        n2 = (CC * CC) / 2;
        f2h_kernel<<<(n2 + 255) / 256, 256>>>((const float2*)w_proj, (__half2*)wph, n2);
        rope_table_kernel<<<(TT * 64 + 255) / 256, 256>>>(rope);
    }

    // 1) QKV projection + fused RoPE -> fp16 qkv
    gemm_h_kernel<<<dim3(NQKV / 128, MROWS / 128), 256, GEMM_SMEM_BYTES>>>(
        xh, wah, b_att, qkvh, rope, 1, MROWS, NQKV, CC);

    // 2) Transpose V section -> [b][h][d][t]
    vtrans_kernel<<<dim3(TT / 32, HDD / 32, BB * NHH), dim3(32, 8)>>>(qkvh, vth);

    // 3) Causal flash attention -> yh [B,T,C] fp16
    flash_h_kernel<<<dim3(TT / 64, BB * NHH), 256, FLASH_SMEM_BYTES>>>(qkvh, vth, yh);

    // 4) Output projection: out = y @ w_proj^T + b_proj (fp32 out)
    gemm_h_kernel<<<dim3(CC / 128, MROWS / 128), 256, GEMM_SMEM_BYTES>>>(
        yh, wph, b_proj, out, rope, 0, MROWS, CC, CC);
}